// round 15
// baseline (speedup 1.0000x reference)
#include <cuda_runtime.h>
#include <math.h>
#include <stdint.h>

#define Bdim 2
#define Ldim 1024
#define Ddim 1024
#define Hdim 16
#define HDdim 64
#define DFFdim 4096
#define WINv 128
#define DILv 4
#define KLAT 64
#define MMEM 64
#define EPSV 1e-6f

#define BLD (Bdim*Ldim*Ddim)
#define BKD (Bdim*KLAT*Ddim)
#define BMD (Bdim*MMEM*Ddim)

// ---------------- scratch (static device memory; no allocations) -------------
__device__ float g_h[BLD];
__device__ float g_qn[BLD];
__device__ float g_kn[BLD];
__device__ float g_qn2[BLD];
__device__ float g_kn2[BLD];
__device__ float g_qn3[BLD];
__device__ float g_kn3[BLD];
__device__ float g_Qa[BLD];
__device__ float g_KVa[(size_t)Bdim*Ldim*2*Ddim];
__device__ float g_Oa[BLD];
__device__ float g_parta[(size_t)2048*1024*2];
__device__ float g_Qb[BLD];
__device__ float g_KVb[(size_t)Bdim*Ldim*2*Ddim];
__device__ float g_Ob[BLD];
__device__ float g_partb[(size_t)2048*1024*2];
__device__ float g_oL[BLD];
__device__ float g_oD[BLD];
__device__ float g_xlat[BLD];
__device__ float g_xmem[BLD];
__device__ float g_x1[BLD];
__device__ float g_hn[BLD];
__device__ float g_latprev[BKD];
__device__ float g_lat[BKD];
__device__ float g_latq[BKD];
__device__ float g_latk[BKD];
__device__ float g_memprev[BMD];
__device__ float g_mem[BMD];
__device__ float g_memq[BMD];
__device__ float g_memk[BMD];
__device__ float g_memdelta[BMD];
__device__ float g_u[(size_t)Bdim*Ldim*2*DFFdim];
__device__ float g_gact[(size_t)Bdim*Ldim*DFFdim];

// ---------------- rmsnorm ----------------------------------------------------
__global__ void rmsnorm_k(const float* __restrict__ x, const float* __restrict__ w,
                          float* __restrict__ o) {
    int row = blockIdx.x;
    const float* xr = x + (size_t)row * Ddim;
    float* orow = o + (size_t)row * Ddim;
    int tid = threadIdx.x;          // 256 threads
    float v[4];
    float s = 0.f;
#pragma unroll
    for (int i = 0; i < 4; i++) { v[i] = xr[tid + i*256]; s += v[i]*v[i]; }
    __shared__ float red[8];
#pragma unroll
    for (int off = 16; off; off >>= 1) s += __shfl_xor_sync(0xffffffffu, s, off);
    if ((tid & 31) == 0) red[tid >> 5] = s;
    __syncthreads();
    float tot = 0.f;
#pragma unroll
    for (int i = 0; i < 8; i++) tot += red[i];
    float scale = rsqrtf(tot * (1.0f/Ddim) + EPSV);
#pragma unroll
    for (int i = 0; i < 4; i++) orow[tid + i*256] = w[tid + i*256] * (v[i] * scale);
}

// ---------------- tf32 mma helpers -------------------------------------------
__device__ __forceinline__ uint32_t f2tf(float f) {
    uint32_t u;
    asm("cvt.rna.tf32.f32 %0, %1;" : "=r"(u) : "f"(f));
    return u;
}
__device__ __forceinline__ void mma_tf32(float* c, const uint32_t* a, const uint32_t* b) {
    asm volatile("mma.sync.aligned.m16n8k8.row.col.f32.tf32.tf32.f32 "
        "{%0,%1,%2,%3}, {%4,%5,%6,%7}, {%8,%9}, {%0,%1,%2,%3};"
        : "+f"(c[0]), "+f"(c[1]), "+f"(c[2]), "+f"(c[3])
        : "r"(a[0]), "r"(a[1]), "r"(a[2]), "r"(a[3]), "r"(b[0]), "r"(b[1]));
}
__device__ __forceinline__ void ldsm4(uint32_t& r0, uint32_t& r1, uint32_t& r2, uint32_t& r3,
                                      uint32_t addr) {
    asm volatile("ldmatrix.sync.aligned.m8n8.x4.shared.b16 {%0,%1,%2,%3}, [%4];"
        : "=r"(r0), "=r"(r1), "=r"(r2), "=r"(r3) : "r"(addr));
}
__device__ __forceinline__ void cp16(uint32_t dst, const void* src) {
    asm volatile("cp.async.cg.shared.global [%0], [%1], 16;" :: "r"(dst), "l"(src));
}
__device__ __forceinline__ void cp_commit() {
    asm volatile("cp.async.commit_group;");
}
template <int N>
__device__ __forceinline__ void cp_wait() {
    asm volatile("cp.async.wait_group %0;" :: "n"(N));
}

// ---------------- GEMM 128x128, 256 thr, cp.async 4-stage, ldmatrix ----------
#define GSTAGE 4
#define GTILEF (128*20)
#define GEMM_SMEM (GSTAGE*GTILEF*2*4)
__global__ void __launch_bounds__(256, 2) gemm128(
    const float* __restrict__ A, const float* __restrict__ Bm,
    const float* __restrict__ res, float* __restrict__ C,
    int M, int N, int K, int Kc) {
    extern __shared__ float smg[];
    float* As = smg;
    float* Bs = smg + GSTAGE*GTILEF;
    int tid = threadIdx.x, lane = tid & 31, wid = tid >> 5;
    int bm = blockIdx.y * 128, bn = blockIdx.x * 128;
    int wm = (wid & 1) * 64, wn = (wid >> 1) * 32;
    int k0base = blockIdx.z * Kc;
    float* Cw = C + (size_t)blockIdx.z * M * N;

    int lrow = tid >> 1;
    int lkq  = (tid & 1) * 8;
    const float* Ag = A + (size_t)(bm + lrow) * K + k0base + lkq;
    const float* Bg = Bm + (size_t)(bn + lrow) * K + k0base + lkq;
    uint32_t sA = (uint32_t)__cvta_generic_to_shared(As) + (lrow*20 + lkq)*4;
    uint32_t sB = (uint32_t)__cvta_generic_to_shared(Bs) + (lrow*20 + lkq)*4;

    // ldmatrix per-lane base addresses (tf32-as-b16pair trick)
    int rowA = (lane & 7) + ((lane >> 3) & 1) * 8;
    int kA   = (lane >> 4) * 4;
    int rowB = (lane & 7) + (lane >> 4) * 8;
    int kB   = ((lane >> 3) & 1) * 4;
    uint32_t aLd = (uint32_t)__cvta_generic_to_shared(As) + ((wm + rowA)*20 + kA)*4;
    uint32_t bLd = (uint32_t)__cvta_generic_to_shared(Bs) + ((wn + rowB)*20 + kB)*4;

    float c[4][4][4] = {};
    int ntiles = Kc >> 4;

    // prologue: issue stages 0..2, one commit group each
#pragma unroll
    for (int s = 0; s < 3; s++) {
        if (s < ntiles) {
            const float* Ap = Ag + (size_t)s*16;
            const float* Bp = Bg + (size_t)s*16;
            uint32_t aOff = sA + s*GTILEF*4;
            uint32_t bOff = sB + s*GTILEF*4;
            cp16(aOff, Ap); cp16(aOff + 16, Ap + 4);
            cp16(bOff, Bp); cp16(bOff + 16, Bp + 4);
        }
        cp_commit();
    }

    for (int kt = 0; kt < ntiles; kt++) {
        cp_wait<2>();      // stage kt complete; kt+1, kt+2 may be in flight
        __syncthreads();   // single barrier per tile
        if (kt + 3 < ntiles) {
            int s = (kt + 3) % GSTAGE;
            const float* Ap = Ag + (size_t)(kt+3)*16;
            const float* Bp = Bg + (size_t)(kt+3)*16;
            cp16(sA + s*GTILEF*4, Ap); cp16(sA + s*GTILEF*4 + 16, Ap + 4);
            cp16(sB + s*GTILEF*4, Bp); cp16(sB + s*GTILEF*4 + 16, Bp + 4);
        }
        cp_commit();

        uint32_t stOff = (uint32_t)(kt % GSTAGE) * GTILEF * 4;
#pragma unroll
        for (int ks = 0; ks < 2; ks++) {
            uint32_t ksOff = stOff + ks * 32;   // 8 floats = 32 bytes
            uint32_t a[4][4], b[4][2];
#pragma unroll
            for (int mt = 0; mt < 4; mt++)
                ldsm4(a[mt][0], a[mt][1], a[mt][2], a[mt][3],
                      aLd + ksOff + mt * 1280);  // 16 rows * 80B
            ldsm4(b[0][0], b[0][1], b[1][0], b[1][1], bLd + ksOff);
            ldsm4(b[2][0], b[2][1], b[3][0], b[3][1], bLd + ksOff + 1280);
#pragma unroll
            for (int mt = 0; mt < 4; mt++)
#pragma unroll
                for (int nt = 0; nt < 4; nt++)
                    mma_tf32(c[mt][nt], a[mt], b[nt]);
        }
        // no trailing sync: next iteration's top barrier provides the ordering
    }

#pragma unroll
    for (int mt = 0; mt < 4; mt++) {
        int r0 = bm + wm + mt*16 + (lane >> 2);
#pragma unroll
        for (int nt = 0; nt < 4; nt++) {
            int cc = bn + wn + nt*8 + (lane & 3)*2;
            float2 v0 = make_float2(c[mt][nt][0], c[mt][nt][1]);
            float2 v1 = make_float2(c[mt][nt][2], c[mt][nt][3]);
            if (res) {
                float2 q0 = *reinterpret_cast<const float2*>(&res[(size_t)r0*N + cc]);
                float2 q1 = *reinterpret_cast<const float2*>(&res[(size_t)(r0+8)*N + cc]);
                v0.x += q0.x; v0.y += q0.y; v1.x += q1.x; v1.y += q1.y;
            }
            *reinterpret_cast<float2*>(&Cw[(size_t)r0*N + cc]) = v0;
            *reinterpret_cast<float2*>(&Cw[(size_t)(r0+8)*N + cc]) = v1;
        }
    }
}

// ---------------- GEMM 64x64, 128 thr, split-K (small M) ---------------------
__global__ void __launch_bounds__(128, 4) gemm64(
    const float* __restrict__ A, const float* __restrict__ Bm,
    float* __restrict__ C, int M, int N, int K, int Kc) {
    __shared__ uint32_t As[2][64][20];
    __shared__ uint32_t Bs[2][64][20];
    int tid = threadIdx.x, lane = tid & 31, wid = tid >> 5;
    int bm = blockIdx.y * 64, bn = blockIdx.x * 64;
    int wm = (wid & 1) * 32, wn = (wid >> 1) * 32;
    int k0base = blockIdx.z * Kc;
    float* Cw = C + (size_t)blockIdx.z * M * N;

    int lrow = tid >> 1;
    int lkq  = (tid & 1) * 8;
    const float* Ag = A + (size_t)(bm + lrow) * K + k0base + lkq;
    const float* Bg = Bm + (size_t)(bn + lrow) * K + k0base + lkq;

    float c[2][4][4] = {};
    int ntiles = Kc >> 4;

    float4 la0, la1, lb0, lb1;
    la0 = *reinterpret_cast<const float4*>(Ag);
    la1 = *reinterpret_cast<const float4*>(Ag + 4);
    lb0 = *reinterpret_cast<const float4*>(Bg);
    lb1 = *reinterpret_cast<const float4*>(Bg + 4);
    As[0][lrow][lkq+0] = f2tf(la0.x); As[0][lrow][lkq+1] = f2tf(la0.y);
    As[0][lrow][lkq+2] = f2tf(la0.z); As[0][lrow][lkq+3] = f2tf(la0.w);
    As[0][lrow][lkq+4] = f2tf(la1.x); As[0][lrow][lkq+5] = f2tf(la1.y);
    As[0][lrow][lkq+6] = f2tf(la1.z); As[0][lrow][lkq+7] = f2tf(la1.w);
    Bs[0][lrow][lkq+0] = f2tf(lb0.x); Bs[0][lrow][lkq+1] = f2tf(lb0.y);
    Bs[0][lrow][lkq+2] = f2tf(lb0.z); Bs[0][lrow][lkq+3] = f2tf(lb0.w);
    Bs[0][lrow][lkq+4] = f2tf(lb1.x); Bs[0][lrow][lkq+5] = f2tf(lb1.y);
    Bs[0][lrow][lkq+6] = f2tf(lb1.z); Bs[0][lrow][lkq+7] = f2tf(lb1.w);
    __syncthreads();

    for (int kt = 0; kt < ntiles; kt++) {
        int cur = kt & 1;
        if (kt + 1 < ntiles) {
            const float* Ap = Ag + (size_t)(kt+1)*16;
            const float* Bp = Bg + (size_t)(kt+1)*16;
            la0 = *reinterpret_cast<const float4*>(Ap);
            la1 = *reinterpret_cast<const float4*>(Ap + 4);
            lb0 = *reinterpret_cast<const float4*>(Bp);
            lb1 = *reinterpret_cast<const float4*>(Bp + 4);
        }
#pragma unroll
        for (int ks = 0; ks < 2; ks++) {
            int kb = ks*8 + (lane & 3);
            int rA = wm + (lane >> 2);
            int rB = wn + (lane >> 2);
            uint32_t a[2][4], b[4][2];
#pragma unroll
            for (int mt = 0; mt < 2; mt++) {
                a[mt][0] = As[cur][rA + mt*16    ][kb];
                a[mt][1] = As[cur][rA + mt*16 + 8][kb];
                a[mt][2] = As[cur][rA + mt*16    ][kb+4];
                a[mt][3] = As[cur][rA + mt*16 + 8][kb+4];
            }
#pragma unroll
            for (int nt = 0; nt < 4; nt++) {
                b[nt][0] = Bs[cur][rB + nt*8][kb];
                b[nt][1] = Bs[cur][rB + nt*8][kb+4];
            }
#pragma unroll
            for (int mt = 0; mt < 2; mt++)
#pragma unroll
                for (int nt = 0; nt < 4; nt++)
                    mma_tf32(c[mt][nt], a[mt], b[nt]);
        }
        if (kt + 1 < ntiles) {
            int nxt = cur ^ 1;
            As[nxt][lrow][lkq+0] = f2tf(la0.x); As[nxt][lrow][lkq+1] = f2tf(la0.y);
            As[nxt][lrow][lkq+2] = f2tf(la0.z); As[nxt][lrow][lkq+3] = f2tf(la0.w);
            As[nxt][lrow][lkq+4] = f2tf(la1.x); As[nxt][lrow][lkq+5] = f2tf(la1.y);
            As[nxt][lrow][lkq+6] = f2tf(la1.z); As[nxt][lrow][lkq+7] = f2tf(la1.w);
            Bs[nxt][lrow][lkq+0] = f2tf(lb0.x); Bs[nxt][lrow][lkq+1] = f2tf(lb0.y);
            Bs[nxt][lrow][lkq+2] = f2tf(lb0.z); Bs[nxt][lrow][lkq+3] = f2tf(lb0.w);
            Bs[nxt][lrow][lkq+4] = f2tf(lb1.x); Bs[nxt][lrow][lkq+5] = f2tf(lb1.y);
            Bs[nxt][lrow][lkq+6] = f2tf(lb1.z); Bs[nxt][lrow][lkq+7] = f2tf(lb1.w);
        }
        __syncthreads();
    }

#pragma unroll
    for (int mt = 0; mt < 2; mt++) {
        int r0 = bm + wm + mt*16 + (lane >> 2);
#pragma unroll
        for (int nt = 0; nt < 4; nt++) {
            int cc = bn + wn + nt*8 + (lane & 3)*2;
            *reinterpret_cast<float2*>(&Cw[(size_t)r0*N + cc]) =
                make_float2(c[mt][nt][0], c[mt][nt][1]);
            *reinterpret_cast<float2*>(&Cw[(size_t)(r0+8)*N + cc]) =
                make_float2(c[mt][nt][2], c[mt][nt][3]);
        }
    }
}

// ---------------- split-K reduce ----------------------------------------------
__global__ void reduce_splitk(const float* __restrict__ part, const float* __restrict__ res,
                              float* __restrict__ out, int MN, int SK) {
    int i = blockIdx.x*256 + threadIdx.x;
    if (i >= MN) return;
    float s = res ? res[i] : 0.f;
    for (int k = 0; k < SK; k++) s += part[(size_t)k*MN + i];
    out[i] = s;
}

// ---------------- fused flash attention --------------------------------------
#define ATTN_SMEM (4*64*68*4 + 3*64*4)
__global__ void __launch_bounds__(256, 2) fattn(
    const float* __restrict__ Q, const float* __restrict__ Kg,
    const float* __restrict__ Vg, float* __restrict__ O,
    int lq, int lk, int ldk, int mask_mode, const unsigned char* __restrict__ kpm) {
    extern __shared__ float sm[];
    float (*Qs)[68] = (float(*)[68])sm;
    float (*Ks)[68] = (float(*)[68])(sm + 64*68);
    float (*Vs)[68] = (float(*)[68])(sm + 2*64*68);
    float (*Ps)[68] = (float(*)[68])(sm + 3*64*68);
    float* m_s  = sm + 4*64*68;
    float* l_s  = m_s + 64;
    float* al_s = l_s + 64;

    int tid = threadIdx.x;
    int q0 = blockIdx.x * 64;
    int bh = blockIdx.y;
    int b = bh >> 4, h = bh & 15;

#pragma unroll
    for (int i = 0; i < 4; i++) {
        int id = tid + i*256;
        int r = id >> 4, dq = (id & 15) * 4;
        *reinterpret_cast<float4*>(&Qs[r][dq]) =
            *reinterpret_cast<const float4*>(&Q[((size_t)(b*lq + q0 + r))*Ddim + h*HDdim + dq]);
    }
    if (tid < 64) { m_s[tid] = -INFINITY; l_s[tid] = 0.f; }
    __syncthreads();

    int ty = tid >> 4, tx = tid & 15;
    int r0 = ty * 4;
    float o[4][4] = {};

    int c_lo = 0, c_hi = lk >> 6;
    if (mask_mode) {
        c_lo = (q0 >= WINv) ? (q0 - WINv) >> 6 : 0;
        int hi = (q0 + 64 + WINv) >> 6;
        if (hi < c_hi) c_hi = hi;
    }

    for (int ck = c_lo; ck < c_hi; ck++) {
        int kb = ck * 64;
#pragma unroll
        for (int i = 0; i < 4; i++) {
            int id = tid + i*256;
            int r = id >> 4, dq = (id & 15)*4;
            size_t g = ((size_t)(b*lk + kb + r))*ldk + h*HDdim + dq;
            *reinterpret_cast<float4*>(&Ks[r][dq]) = *reinterpret_cast<const float4*>(&Kg[g]);
            *reinterpret_cast<float4*>(&Vs[r][dq]) = *reinterpret_cast<const float4*>(&Vg[g]);
        }
        __syncthreads();

        float s[4][4] = {};
#pragma unroll
        for (int k = 0; k < 64; k += 4) {
            float4 qv[4], kv[4];
#pragma unroll
            for (int i = 0; i < 4; i++) qv[i] = *reinterpret_cast<float4*>(&Qs[r0+i][k]);
#pragma unroll
            for (int j = 0; j < 4; j++) kv[j] = *reinterpret_cast<float4*>(&Ks[tx + 16*j][k]);
#pragma unroll
            for (int i = 0; i < 4; i++)
#pragma unroll
                for (int j = 0; j < 4; j++)
                    s[i][j] += qv[i].x*kv[j].x + qv[i].y*kv[j].y
                             + qv[i].z*kv[j].z + qv[i].w*kv[j].w;
        }
#pragma unroll
        for (int i = 0; i < 4; i++) {
            int qr = q0 + r0 + i;
#pragma unroll
            for (int j = 0; j < 4; j++) {
                int col = kb + tx + 16*j;
                float v = s[i][j] * 0.125f;
                int jr = col - qr;
                bool ok = true;
                if (mask_mode == 1) ok = (jr <= WINv && jr >= -WINv);
                else if (mask_mode == 2) ok = (jr <= WINv && jr >= -WINv && ((jr & 3) == 0));
                if (kpm && kpm[b*lk + col]) ok = false;
                Ps[r0+i][tx + 16*j] = ok ? v : -INFINITY;
            }
        }
        __syncthreads();

        {
            int w = tid >> 5, ln = tid & 31;
            for (int rr = w*8; rr < w*8 + 8; rr++) {
                float s0 = Ps[rr][ln], s1 = Ps[rr][ln+32];
                float mx = fmaxf(s0, s1);
#pragma unroll
                for (int off = 16; off; off >>= 1)
                    mx = fmaxf(mx, __shfl_xor_sync(0xffffffffu, mx, off));
                float mo = m_s[rr];
                float mn = fmaxf(mo, mx);
                float p0, p1, alpha;
                if (mn == -INFINITY) { p0 = 0.f; p1 = 0.f; alpha = 1.f; }
                else {
                    alpha = __expf(mo - mn);
                    p0 = (s0 == -INFINITY) ? 0.f : __expf(s0 - mn);
                    p1 = (s1 == -INFINITY) ? 0.f : __expf(s1 - mn);
                }
                Ps[rr][ln] = p0; Ps[rr][ln+32] = p1;
                float sum = p0 + p1;
#pragma unroll
                for (int off = 16; off; off >>= 1)
                    sum += __shfl_xor_sync(0xffffffffu, sum, off);
                if (ln == 0) {
                    l_s[rr] = l_s[rr]*alpha + sum;
                    m_s[rr] = mn;
                    al_s[rr] = alpha;
                }
            }
        }
        __syncthreads();

#pragma unroll
        for (int i = 0; i < 4; i++) {
            float a = al_s[r0+i];
#pragma unroll
            for (int j = 0; j < 4; j++) o[i][j] *= a;
        }
#pragma unroll
        for (int k = 0; k < 64; k += 4) {
            float4 pk[4];
#pragma unroll
            for (int i = 0; i < 4; i++) pk[i] = *reinterpret_cast<float4*>(&Ps[r0+i][k]);
#pragma unroll
            for (int kk = 0; kk < 4; kk++) {
                float4 vv = *reinterpret_cast<float4*>(&Vs[k+kk][tx*4]);
#pragma unroll
                for (int i = 0; i < 4; i++) {
                    float p = (kk == 0) ? pk[i].x : (kk == 1) ? pk[i].y : (kk == 2) ? pk[i].z : pk[i].w;
                    o[i][0] += p*vv.x; o[i][1] += p*vv.y; o[i][2] += p*vv.z; o[i][3] += p*vv.w;
                }
            }
        }
        __syncthreads();
    }

#pragma unroll
    for (int i = 0; i < 4; i++) {
        float inv = 1.0f / l_s[r0+i];
        float4 ov = make_float4(o[i][0]*inv, o[i][1]*inv, o[i][2]*inv, o[i][3]*inv);
        *reinterpret_cast<float4*>(&O[((size_t)(b*lq + q0 + r0 + i))*Ddim + h*HDdim + tx*4]) = ov;
    }
}

// ---------------- fused gate + residual + rmsnorm ----------------------------
__global__ void gate_fuse_norm(const float* __restrict__ x, const float* __restrict__ h,
                               const float* __restrict__ o0, const float* __restrict__ o1,
                               const float* __restrict__ o2, const float* __restrict__ o3,
                               const float* __restrict__ gw, const float* __restrict__ gb,
                               const float* __restrict__ nw,
                               float* __restrict__ x1, float* __restrict__ hn) {
    int row = blockIdx.x;
    int tid = threadIdx.x;          // 256
    int warp = tid >> 5, lane = tid & 31;
    __shared__ float wsh[4];
    __shared__ float red[8];
    size_t base = (size_t)row * Ddim;
    const float* hr = h + base;

    if (warp < 4) {
        float p = 0.f;
        const float* gwr = gw + warp * Ddim;
        for (int dd = lane; dd < Ddim; dd += 32) p += hr[dd] * gwr[dd];
#pragma unroll
        for (int off = 16; off; off >>= 1) p += __shfl_down_sync(0xffffffffu, p, off);
        if (lane == 0) wsh[warp] = p + gb[warp];
    }
    __syncthreads();
    if (tid == 0) {
        float mx = fmaxf(fmaxf(wsh[0], wsh[1]), fmaxf(wsh[2], wsh[3]));
        float e0 = expf(wsh[0]-mx), e1 = expf(wsh[1]-mx), e2 = expf(wsh[2]-mx), e3 = expf(wsh[3]-mx);
        float inv = 1.0f / (e0+e1+e2+e3);
        wsh[0] = e0*inv; wsh[1] = e1*inv; wsh[2] = e2*inv; wsh[3] = e3*inv;
    }
    __syncthreads();
    float w0 = wsh[0], w1 = wsh[1], w2 = wsh[2], w3 = wsh[3];

    float v[4];
    float ss = 0.f;
#pragma unroll
    for (int i = 0; i < 4; i++) {
        int dd = tid + i*256;
        float f = x[base+dd] + w0*o0[base+dd] + w1*o1[base+dd]
                             + w2*o2[base+dd] + w3*o3[base+dd];
        v[i] = f;
        ss += f*f;
        x1[base+dd] = f;
    }
#pragma unroll
    for (int off = 16; off; off >>= 1) ss += __shfl_xor_sync(0xffffffffu, ss, off);
    if (lane == 0) red[warp] = ss;
    __syncthreads();
    float tot = 0.f;
#pragma unroll
    for (int i = 0; i < 8; i++) tot += red[i];
    float scale = rsqrtf(tot * (1.0f/Ddim) + EPSV);
#pragma unroll
    for (int i = 0; i < 4; i++) {
        int dd = tid + i*256;
        hn[base+dd] = nw[dd] * (v[i] * scale);
    }
}

// ---------------- elementwise helpers ----------------------------------------
__global__ void broadcast_k(const float* __restrict__ src, float* __restrict__ dst,
                            int mask, int total) {
    int i = blockIdx.x*256 + threadIdx.x;
    if (i < total) dst[i] = src[i & mask];
}
__global__ void ema_k(const float* __restrict__ prev, const float* __restrict__ delta,
                      float* __restrict__ mem, int n) {
    int i = blockIdx.x*256 + threadIdx.x;
    if (i < n) mem[i] = 0.9f*prev[i] + 0.1f*(prev[i] + delta[i]);
}
// float4 silu*gate with fast exp
__global__ void silu_mul_k(const float* __restrict__ u, float* __restrict__ o, int n4) {
    int i = blockIdx.x*256 + threadIdx.x;
    if (i < n4) {
        int r = i >> 10;
        int f4 = i & 1023;
        const float4 a = *reinterpret_cast<const float4*>(&u[((size_t)r << 13) + f4*4]);
        const float4 g = *reinterpret_cast<const float4*>(&u[((size_t)r << 13) + DFFdim + f4*4]);
        float4 ov;
        ov.x = (a.x / (1.0f + __expf(-a.x))) * g.x;
        ov.y = (a.y / (1.0f + __expf(-a.y))) * g.y;
        ov.z = (a.z / (1.0f + __expf(-a.z))) * g.z;
        ov.w = (a.w / (1.0f + __expf(-a.w))) * g.w;
        *reinterpret_cast<float4*>(&o[(size_t)i*4]) = ov;
    }
}
__global__ void copy_k(const float* __restrict__ src, float* __restrict__ dst, int n) {
    int i = blockIdx.x*256 + threadIdx.x;
    if (i < n) dst[i] = src[i];
}

#define SYMF(name) ({ void* _p = nullptr; cudaGetSymbolAddress(&_p, name); (float*)_p; })

// generic projection: C[M,N] = A @ W^T (+res)
static void proj(const float* A, const float* W, const float* res, float* C,
                 float* partB, int M, int N, int K, cudaStream_t st) {
    if (M >= 1024) {
        gemm128<<<dim3(N/128, M/128, 1), 256, GEMM_SMEM, st>>>(A, W, res, C, M, N, K, K);
    } else {
        const int SK = 4;
        gemm64<<<dim3(N/64, M/64, SK), 128, 0, st>>>(A, W, partB, M, N, K, K/SK);
        int MN = M*N;
        reduce_splitk<<<(MN+255)/256, 256, 0, st>>>(partB, res, C, MN, SK);
    }
}

static void run_mha(const float* qin, const float* kvin, const float* w,
                    int lq, int lk, int mask_mode, const unsigned char* kpm,
                    const float* res, float* out,
                    float* Qb, float* KVb, float* Ob, float* partB, cudaStream_t st) {
    const float* Wq = w;
    const float* Wkv = w + Ddim*Ddim;
    const float* Wo = w + 3*Ddim*Ddim;
    int Mq = Bdim * lq, Mk = Bdim * lk;
    proj(qin, Wq, nullptr, Qb, partB, Mq, Ddim, Ddim, st);
    proj(kvin, Wkv, nullptr, KVb, partB, Mk, 2*Ddim, Ddim, st);
    fattn<<<dim3(lq/64, Bdim*Hdim), 256, ATTN_SMEM, st>>>(Qb, KVb, KVb + Ddim, Ob,
                                                          lq, lk, 2*Ddim, mask_mode, kpm);
    proj(Ob, Wo, res, out, partB, Mq, Ddim, Ddim, st);
}

extern "C" void kernel_launch(void* const* d_in, const int* in_sizes, int n_in,
                              void* d_out, int out_size) {
    const float* x          = (const float*)d_in[0];
    const unsigned char* kpm = (const unsigned char*)d_in[1];
    const float* norm_w     = (const float*)d_in[2];
    const float* ld_nq      = (const float*)d_in[3];
    const float* ld_nk      = (const float*)d_in[4];
    const float* local_w    = (const float*)d_in[5];
    const float* dil_w      = (const float*)d_in[6];
    const float* lat_tokens = (const float*)d_in[7];
    const float* lp_nq      = (const float*)d_in[8];
    const float* lp_nk      = (const float*)d_in[9];
    const float* lat_to_w   = (const float*)d_in[10];
    const float* lat_from_w = (const float*)d_in[11];
    const float* mem_tokens = (const float*)d_in[12];
    const float* mem_nq     = (const float*)d_in[13];
    const float* mem_nk     = (const float*)d_in[14];
    const float* mem_read_w = (const float*)d_in[15];
    const float* mem_write_w= (const float*)d_in[16];
    const float* gate_w     = (const float*)d_in[17];
    const float* gate_b     = (const float*)d_in[18];
    const float* up_w       = (const float*)d_in[19];
    const float* down_w     = (const float*)d_in[20];
    float* out = (float*)d_out;

    static cudaStream_t sA = nullptr, sB = nullptr;
    static cudaEvent_t evFork = nullptr, evA = nullptr, evB = nullptr;
    static cudaEvent_t evQ = nullptr, evK = nullptr;
    if (!sA) {
        cudaStreamCreateWithFlags(&sA, cudaStreamNonBlocking);
        cudaStreamCreateWithFlags(&sB, cudaStreamNonBlocking);
        cudaEventCreateWithFlags(&evFork, cudaEventDisableTiming);
        cudaEventCreateWithFlags(&evA, cudaEventDisableTiming);
        cudaEventCreateWithFlags(&evB, cudaEventDisableTiming);
        cudaEventCreateWithFlags(&evQ, cudaEventDisableTiming);
        cudaEventCreateWithFlags(&evK, cudaEventDisableTiming);
        cudaFuncSetAttribute(fattn, cudaFuncAttributeMaxDynamicSharedMemorySize, ATTN_SMEM);
        cudaFuncSetAttribute(gemm128, cudaFuncAttributeMaxDynamicSharedMemorySize, GEMM_SMEM);
    }

    float* hB   = SYMF(g_h);
    float* qnB  = SYMF(g_qn);
    float* knB  = SYMF(g_kn);
    float* qn2B = SYMF(g_qn2);
    float* kn2B = SYMF(g_kn2);
    float* qn3B = SYMF(g_qn3);
    float* kn3B = SYMF(g_kn3);
    float* QaB  = SYMF(g_Qa);
    float* KVaB = SYMF(g_KVa);
    float* OaB  = SYMF(g_Oa);
    float* partaB = SYMF(g_parta);
    float* QbB  = SYMF(g_Qb);
    float* KVbB = SYMF(g_KVb);
    float* ObB  = SYMF(g_Ob);
    float* partbB = SYMF(g_partb);
    float* oLB  = SYMF(g_oL);
    float* oDB  = SYMF(g_oD);
    float* xlatB= SYMF(g_xlat);
    float* xmemB= SYMF(g_xmem);
    float* x1B  = SYMF(g_x1);
    float* hnB  = SYMF(g_hn);
    float* latprevB = SYMF(g_latprev);
    float* latB  = SYMF(g_lat);
    float* latqB = SYMF(g_latq);
    float* latkB = SYMF(g_latk);
    float* memprevB = SYMF(g_memprev);
    float* memB  = SYMF(g_mem);
    float* memqB = SYMF(g_memq);
    float* memkB = SYMF(g_memk);
    float* memdB = SYMF(g_memdelta);
    float* uB    = SYMF(g_u);
    float* gactB = SYMF(g_gact);

    const int rowsBL = Bdim * Ldim;

    // prologue: h on default; qn/kn split across workers
    rmsnorm_k<<<rowsBL, 256>>>(x, norm_w, hB);
    cudaEventRecord(evFork, 0);
    cudaStreamWaitEvent(sA, evFork, 0);
    cudaStreamWaitEvent(sB, evFork, 0);
    rmsnorm_k<<<rowsBL, 256, 0, sA>>>(hB, ld_nq, qnB);
    cudaEventRecord(evQ, sA);
    rmsnorm_k<<<rowsBL, 256, 0, sB>>>(hB, ld_nk, knB);
    cudaEventRecord(evK, sB);
    cudaStreamWaitEvent(sA, evK, 0);
    cudaStreamWaitEvent(sB, evQ, 0);

    // ---- stream A: local branch, then latent chain ----
    run_mha(qnB, knB, local_w, Ldim, Ldim, 1, kpm, nullptr, oLB, QaB, KVaB, OaB, partaB, sA);

    broadcast_k<<<(BKD+255)/256, 256, 0, sA>>>(lat_tokens, latprevB, KLAT*Ddim - 1, BKD);
    rmsnorm_k<<<Bdim*KLAT, 256, 0, sA>>>(latprevB, lp_nq, latqB);
    rmsnorm_k<<<rowsBL, 256, 0, sA>>>(hB, lp_nk, kn2B);
    run_mha(latqB, kn2B, lat_to_w, KLAT, Ldim, 0, kpm, latprevB, latB, QaB, KVaB, OaB, partaB, sA);
    rmsnorm_k<<<rowsBL, 256, 0, sA>>>(hB, lp_nq, qn2B);
    rmsnorm_k<<<Bdim*KLAT, 256, 0, sA>>>(latB, lp_nk, latkB);
    run_mha(qn2B, latkB, lat_from_w, Ldim, KLAT, 0, nullptr, hB, xlatB, QaB, KVaB, OaB, partaB, sA);
    copy_k<<<(BKD+255)/256, 256, 0, sA>>>(latB, out + (size_t)BLD, BKD);
    cudaEventRecord(evA, sA);

    // ---- stream B: dilated branch, then memory chain ----
    run_mha(qnB, knB, dil_w, Ldim, Ldim, 2, kpm, nullptr, oDB, QbB, KVbB, ObB, partbB, sB);

    broadcast_k<<<(BMD+255)/256, 256, 0, sB>>>(mem_tokens, memprevB, MMEM*Ddim - 1, BMD);
    rmsnorm_k<<<Bdim*MMEM, 256, 0, sB>>>(memprevB, mem_nq, memqB);
    rmsnorm_k<<<rowsBL, 256, 0, sB>>>(hB, mem_nk, kn3B);
    run_mha(memqB, kn3B, mem_write_w, MMEM, Ldim, 0, kpm, nullptr, memdB, QbB, KVbB, ObB, partbB, sB);
    ema_k<<<(BMD+255)/256, 256, 0, sB>>>(memprevB, memdB, memB, BMD);
    rmsnorm_k<<<rowsBL, 256, 0, sB>>>(hB, mem_nq, qn3B);
    rmsnorm_k<<<Bdim*MMEM, 256, 0, sB>>>(memB, mem_nk, memkB);
    run_mha(qn3B, memkB, mem_read_w, Ldim, MMEM, 0, nullptr, hB, xmemB, QbB, KVbB, ObB, partbB, sB);
    copy_k<<<(BMD+255)/256, 256, 0, sB>>>(memB, out + (size_t)BLD + BKD, BMD);
    cudaEventRecord(evB, sB);

    // ---- join, then fused gate+norm + FFN on the capture stream ----
    cudaStreamWaitEvent(0, evA, 0);
    cudaStreamWaitEvent(0, evB, 0);

    gate_fuse_norm<<<rowsBL, 256>>>(x, hB, oLB, oDB, xlatB, xmemB,
                                    gate_w, gate_b, norm_w, x1B, hnB);

    gemm128<<<dim3(2*DFFdim/128, rowsBL/128, 1), 256, GEMM_SMEM>>>(hnB, up_w, nullptr, uB,
                                                        rowsBL, 2*DFFdim, Ddim, Ddim);
    int n4 = rowsBL * DFFdim / 4;
    silu_mul_k<<<(n4+255)/256, 256>>>(uB, gactB, n4);
    // direct down-proj: residual fused into out; no partials, no reduce
    gemm128<<<dim3(Ddim/128, rowsBL/128, 1), 256, GEMM_SMEM>>>(gactB, down_w, x1B, out,
                                                    rowsBL, Ddim, DFFdim, DFFdim);
}

// round 16
// speedup vs baseline: 1.0072x; 1.0072x over previous
#include <cuda_runtime.h>
#include <math.h>
#include <stdint.h>

#define Bdim 2
#define Ldim 1024
#define Ddim 1024
#define Hdim 16
#define HDdim 64
#define DFFdim 4096
#define WINv 128
#define DILv 4
#define KLAT 64
#define MMEM 64
#define EPSV 1e-6f

#define BLD (Bdim*Ldim*Ddim)
#define BKD (Bdim*KLAT*Ddim)
#define BMD (Bdim*MMEM*Ddim)

// ---------------- scratch (static device memory; no allocations) -------------
__device__ float g_h[BLD];
__device__ float g_qn[BLD];
__device__ float g_kn[BLD];
__device__ float g_qn2[BLD];
__device__ float g_kn2[BLD];
__device__ float g_qn3[BLD];
__device__ float g_kn3[BLD];
__device__ float g_Qa[BLD];
__device__ float g_KVa[(size_t)Bdim*Ldim*2*Ddim];
__device__ float g_Oa[BLD];
__device__ float g_parta[(size_t)2048*1024*2];
__device__ float g_Qb[BLD];
__device__ float g_KVb[(size_t)Bdim*Ldim*2*Ddim];
__device__ float g_Ob[BLD];
__device__ float g_partb[(size_t)2048*1024*2];
__device__ float g_oL[BLD];
__device__ float g_oD[BLD];
__device__ float g_xlat[BLD];
__device__ float g_xmem[BLD];
__device__ float g_x1[BLD];
__device__ float g_hn[BLD];
__device__ float g_latprev[BKD];
__device__ float g_lat[BKD];
__device__ float g_latq[BKD];
__device__ float g_latk[BKD];
__device__ float g_memprev[BMD];
__device__ float g_mem[BMD];
__device__ float g_memq[BMD];
__device__ float g_memk[BMD];
__device__ float g_memdelta[BMD];
__device__ float g_u[(size_t)Bdim*Ldim*2*DFFdim];
__device__ float g_gact[(size_t)Bdim*Ldim*DFFdim];

// ---------------- rmsnorm ----------------------------------------------------
__global__ void rmsnorm_k(const float* __restrict__ x, const float* __restrict__ w,
                          float* __restrict__ o) {
    int row = blockIdx.x;
    const float* xr = x + (size_t)row * Ddim;
    float* orow = o + (size_t)row * Ddim;
    int tid = threadIdx.x;          // 256 threads
    float v[4];
    float s = 0.f;
#pragma unroll
    for (int i = 0; i < 4; i++) { v[i] = xr[tid + i*256]; s += v[i]*v[i]; }
    __shared__ float red[8];
#pragma unroll
    for (int off = 16; off; off >>= 1) s += __shfl_xor_sync(0xffffffffu, s, off);
    if ((tid & 31) == 0) red[tid >> 5] = s;
    __syncthreads();
    float tot = 0.f;
#pragma unroll
    for (int i = 0; i < 8; i++) tot += red[i];
    float scale = rsqrtf(tot * (1.0f/Ddim) + EPSV);
#pragma unroll
    for (int i = 0; i < 4; i++) orow[tid + i*256] = w[tid + i*256] * (v[i] * scale);
}

// ---------------- rmsnorm of h with 6 weight vectors, one pass ---------------
__global__ void rmsnorm6_k(const float* __restrict__ h,
                           const float* __restrict__ w0, float* __restrict__ o0,
                           const float* __restrict__ w1, float* __restrict__ o1,
                           const float* __restrict__ w2, float* __restrict__ o2,
                           const float* __restrict__ w3, float* __restrict__ o3,
                           const float* __restrict__ w4, float* __restrict__ o4,
                           const float* __restrict__ w5, float* __restrict__ o5) {
    int row = blockIdx.x;
    size_t base = (size_t)row * Ddim;
    int tid = threadIdx.x;          // 256
    float v[4];
    float s = 0.f;
#pragma unroll
    for (int i = 0; i < 4; i++) { v[i] = h[base + tid + i*256]; s += v[i]*v[i]; }
    __shared__ float red[8];
#pragma unroll
    for (int off = 16; off; off >>= 1) s += __shfl_xor_sync(0xffffffffu, s, off);
    if ((tid & 31) == 0) red[tid >> 5] = s;
    __syncthreads();
    float tot = 0.f;
#pragma unroll
    for (int i = 0; i < 8; i++) tot += red[i];
    float scale = rsqrtf(tot * (1.0f/Ddim) + EPSV);
#pragma unroll
    for (int i = 0; i < 4; i++) {
        int dd = tid + i*256;
        float hv = v[i] * scale;
        o0[base+dd] = w0[dd] * hv;
        o1[base+dd] = w1[dd] * hv;
        o2[base+dd] = w2[dd] * hv;
        o3[base+dd] = w3[dd] * hv;
        o4[base+dd] = w4[dd] * hv;
        o5[base+dd] = w5[dd] * hv;
    }
}

// ---------------- tf32 mma helpers -------------------------------------------
__device__ __forceinline__ uint32_t f2tf(float f) {
    uint32_t u;
    asm("cvt.rna.tf32.f32 %0, %1;" : "=r"(u) : "f"(f));
    return u;
}
__device__ __forceinline__ void mma_tf32(float* c, const uint32_t* a, const uint32_t* b) {
    asm volatile("mma.sync.aligned.m16n8k8.row.col.f32.tf32.tf32.f32 "
        "{%0,%1,%2,%3}, {%4,%5,%6,%7}, {%8,%9}, {%0,%1,%2,%3};"
        : "+f"(c[0]), "+f"(c[1]), "+f"(c[2]), "+f"(c[3])
        : "r"(a[0]), "r"(a[1]), "r"(a[2]), "r"(a[3]), "r"(b[0]), "r"(b[1]));
}
__device__ __forceinline__ void ldsm4(uint32_t& r0, uint32_t& r1, uint32_t& r2, uint32_t& r3,
                                      uint32_t addr) {
    asm volatile("ldmatrix.sync.aligned.m8n8.x4.shared.b16 {%0,%1,%2,%3}, [%4];"
        : "=r"(r0), "=r"(r1), "=r"(r2), "=r"(r3) : "r"(addr));
}
__device__ __forceinline__ void cp16(uint32_t dst, const void* src) {
    asm volatile("cp.async.cg.shared.global [%0], [%1], 16;" :: "r"(dst), "l"(src));
}
__device__ __forceinline__ void cp_commit() {
    asm volatile("cp.async.commit_group;");
}
template <int N>
__device__ __forceinline__ void cp_wait() {
    asm volatile("cp.async.wait_group %0;" :: "n"(N));
}

// ---------------- GEMM 128x128, 256 thr, cp.async 4-stage, ldmatrix ----------
#define GSTAGE 4
#define GTILEF (128*20)
#define GEMM_SMEM (GSTAGE*GTILEF*2*4)
__global__ void __launch_bounds__(256, 2) gemm128(
    const float* __restrict__ A, const float* __restrict__ Bm,
    const float* __restrict__ res, float* __restrict__ C,
    int M, int N, int K, int Kc) {
    extern __shared__ float smg[];
    float* As = smg;
    float* Bs = smg + GSTAGE*GTILEF;
    int tid = threadIdx.x, lane = tid & 31, wid = tid >> 5;
    int bm = blockIdx.y * 128, bn = blockIdx.x * 128;
    int wm = (wid & 1) * 64, wn = (wid >> 1) * 32;
    int k0base = blockIdx.z * Kc;
    float* Cw = C + (size_t)blockIdx.z * M * N;

    int lrow = tid >> 1;
    int lkq  = (tid & 1) * 8;
    const float* Ag = A + (size_t)(bm + lrow) * K + k0base + lkq;
    const float* Bg = Bm + (size_t)(bn + lrow) * K + k0base + lkq;
    uint32_t sA = (uint32_t)__cvta_generic_to_shared(As) + (lrow*20 + lkq)*4;
    uint32_t sB = (uint32_t)__cvta_generic_to_shared(Bs) + (lrow*20 + lkq)*4;

    // ldmatrix per-lane base addresses (tf32-as-b16pair trick)
    int rowA = (lane & 7) + ((lane >> 3) & 1) * 8;
    int kA   = (lane >> 4) * 4;
    int rowB = (lane & 7) + (lane >> 4) * 8;
    int kB   = ((lane >> 3) & 1) * 4;
    uint32_t aLd = (uint32_t)__cvta_generic_to_shared(As) + ((wm + rowA)*20 + kA)*4;
    uint32_t bLd = (uint32_t)__cvta_generic_to_shared(Bs) + ((wn + rowB)*20 + kB)*4;

    float c[4][4][4] = {};
    int ntiles = Kc >> 4;

    // prologue: issue stages 0..2, one commit group each
#pragma unroll
    for (int s = 0; s < 3; s++) {
        if (s < ntiles) {
            const float* Ap = Ag + (size_t)s*16;
            const float* Bp = Bg + (size_t)s*16;
            uint32_t aOff = sA + s*GTILEF*4;
            uint32_t bOff = sB + s*GTILEF*4;
            cp16(aOff, Ap); cp16(aOff + 16, Ap + 4);
            cp16(bOff, Bp); cp16(bOff + 16, Bp + 4);
        }
        cp_commit();
    }

    for (int kt = 0; kt < ntiles; kt++) {
        cp_wait<2>();      // stage kt complete; kt+1, kt+2 may be in flight
        __syncthreads();   // single barrier per tile
        if (kt + 3 < ntiles) {
            int s = (kt + 3) % GSTAGE;
            const float* Ap = Ag + (size_t)(kt+3)*16;
            const float* Bp = Bg + (size_t)(kt+3)*16;
            cp16(sA + s*GTILEF*4, Ap); cp16(sA + s*GTILEF*4 + 16, Ap + 4);
            cp16(sB + s*GTILEF*4, Bp); cp16(sB + s*GTILEF*4 + 16, Bp + 4);
        }
        cp_commit();

        uint32_t stOff = (uint32_t)(kt % GSTAGE) * GTILEF * 4;
#pragma unroll
        for (int ks = 0; ks < 2; ks++) {
            uint32_t ksOff = stOff + ks * 32;   // 8 floats = 32 bytes
            uint32_t a[4][4], b[4][2];
#pragma unroll
            for (int mt = 0; mt < 4; mt++)
                ldsm4(a[mt][0], a[mt][1], a[mt][2], a[mt][3],
                      aLd + ksOff + mt * 1280);  // 16 rows * 80B
            ldsm4(b[0][0], b[0][1], b[1][0], b[1][1], bLd + ksOff);
            ldsm4(b[2][0], b[2][1], b[3][0], b[3][1], bLd + ksOff + 1280);
#pragma unroll
            for (int mt = 0; mt < 4; mt++)
#pragma unroll
                for (int nt = 0; nt < 4; nt++)
                    mma_tf32(c[mt][nt], a[mt], b[nt]);
        }
        // no trailing sync: next iteration's top barrier provides the ordering
    }

#pragma unroll
    for (int mt = 0; mt < 4; mt++) {
        int r0 = bm + wm + mt*16 + (lane >> 2);
#pragma unroll
        for (int nt = 0; nt < 4; nt++) {
            int cc = bn + wn + nt*8 + (lane & 3)*2;
            float2 v0 = make_float2(c[mt][nt][0], c[mt][nt][1]);
            float2 v1 = make_float2(c[mt][nt][2], c[mt][nt][3]);
            if (res) {
                float2 q0 = *reinterpret_cast<const float2*>(&res[(size_t)r0*N + cc]);
                float2 q1 = *reinterpret_cast<const float2*>(&res[(size_t)(r0+8)*N + cc]);
                v0.x += q0.x; v0.y += q0.y; v1.x += q1.x; v1.y += q1.y;
            }
            *reinterpret_cast<float2*>(&Cw[(size_t)r0*N + cc]) = v0;
            *reinterpret_cast<float2*>(&Cw[(size_t)(r0+8)*N + cc]) = v1;
        }
    }
}

// ---------------- GEMM 64x64, 128 thr, split-K (small M) ---------------------
__global__ void __launch_bounds__(128, 4) gemm64(
    const float* __restrict__ A, const float* __restrict__ Bm,
    float* __restrict__ C, int M, int N, int K, int Kc) {
    __shared__ uint32_t As[2][64][20];
    __shared__ uint32_t Bs[2][64][20];
    int tid = threadIdx.x, lane = tid & 31, wid = tid >> 5;
    int bm = blockIdx.y * 64, bn = blockIdx.x * 64;
    int wm = (wid & 1) * 32, wn = (wid >> 1) * 32;
    int k0base = blockIdx.z * Kc;
    float* Cw = C + (size_t)blockIdx.z * M * N;

    int lrow = tid >> 1;
    int lkq  = (tid & 1) * 8;
    const float* Ag = A + (size_t)(bm + lrow) * K + k0base + lkq;
    const float* Bg = Bm + (size_t)(bn + lrow) * K + k0base + lkq;

    float c[2][4][4] = {};
    int ntiles = Kc >> 4;

    float4 la0, la1, lb0, lb1;
    la0 = *reinterpret_cast<const float4*>(Ag);
    la1 = *reinterpret_cast<const float4*>(Ag + 4);
    lb0 = *reinterpret_cast<const float4*>(Bg);
    lb1 = *reinterpret_cast<const float4*>(Bg + 4);
    As[0][lrow][lkq+0] = f2tf(la0.x); As[0][lrow][lkq+1] = f2tf(la0.y);
    As[0][lrow][lkq+2] = f2tf(la0.z); As[0][lrow][lkq+3] = f2tf(la0.w);
    As[0][lrow][lkq+4] = f2tf(la1.x); As[0][lrow][lkq+5] = f2tf(la1.y);
    As[0][lrow][lkq+6] = f2tf(la1.z); As[0][lrow][lkq+7] = f2tf(la1.w);
    Bs[0][lrow][lkq+0] = f2tf(lb0.x); Bs[0][lrow][lkq+1] = f2tf(lb0.y);
    Bs[0][lrow][lkq+2] = f2tf(lb0.z); Bs[0][lrow][lkq+3] = f2tf(lb0.w);
    Bs[0][lrow][lkq+4] = f2tf(lb1.x); Bs[0][lrow][lkq+5] = f2tf(lb1.y);
    Bs[0][lrow][lkq+6] = f2tf(lb1.z); Bs[0][lrow][lkq+7] = f2tf(lb1.w);
    __syncthreads();

    for (int kt = 0; kt < ntiles; kt++) {
        int cur = kt & 1;
        if (kt + 1 < ntiles) {
            const float* Ap = Ag + (size_t)(kt+1)*16;
            const float* Bp = Bg + (size_t)(kt+1)*16;
            la0 = *reinterpret_cast<const float4*>(Ap);
            la1 = *reinterpret_cast<const float4*>(Ap + 4);
            lb0 = *reinterpret_cast<const float4*>(Bp);
            lb1 = *reinterpret_cast<const float4*>(Bp + 4);
        }
#pragma unroll
        for (int ks = 0; ks < 2; ks++) {
            int kb = ks*8 + (lane & 3);
            int rA = wm + (lane >> 2);
            int rB = wn + (lane >> 2);
            uint32_t a[2][4], b[4][2];
#pragma unroll
            for (int mt = 0; mt < 2; mt++) {
                a[mt][0] = As[cur][rA + mt*16    ][kb];
                a[mt][1] = As[cur][rA + mt*16 + 8][kb];
                a[mt][2] = As[cur][rA + mt*16    ][kb+4];
                a[mt][3] = As[cur][rA + mt*16 + 8][kb+4];
            }
#pragma unroll
            for (int nt = 0; nt < 4; nt++) {
                b[nt][0] = Bs[cur][rB + nt*8][kb];
                b[nt][1] = Bs[cur][rB + nt*8][kb+4];
            }
#pragma unroll
            for (int mt = 0; mt < 2; mt++)
#pragma unroll
                for (int nt = 0; nt < 4; nt++)
                    mma_tf32(c[mt][nt], a[mt], b[nt]);
        }
        if (kt + 1 < ntiles) {
            int nxt = cur ^ 1;
            As[nxt][lrow][lkq+0] = f2tf(la0.x); As[nxt][lrow][lkq+1] = f2tf(la0.y);
            As[nxt][lrow][lkq+2] = f2tf(la0.z); As[nxt][lrow][lkq+3] = f2tf(la0.w);
            As[nxt][lrow][lkq+4] = f2tf(la1.x); As[nxt][lrow][lkq+5] = f2tf(la1.y);
            As[nxt][lrow][lkq+6] = f2tf(la1.z); As[nxt][lrow][lkq+7] = f2tf(la1.w);
            Bs[nxt][lrow][lkq+0] = f2tf(lb0.x); Bs[nxt][lrow][lkq+1] = f2tf(lb0.y);
            Bs[nxt][lrow][lkq+2] = f2tf(lb0.z); Bs[nxt][lrow][lkq+3] = f2tf(lb0.w);
            Bs[nxt][lrow][lkq+4] = f2tf(lb1.x); Bs[nxt][lrow][lkq+5] = f2tf(lb1.y);
            Bs[nxt][lrow][lkq+6] = f2tf(lb1.z); Bs[nxt][lrow][lkq+7] = f2tf(lb1.w);
        }
        __syncthreads();
    }

#pragma unroll
    for (int mt = 0; mt < 2; mt++) {
        int r0 = bm + wm + mt*16 + (lane >> 2);
#pragma unroll
        for (int nt = 0; nt < 4; nt++) {
            int cc = bn + wn + nt*8 + (lane & 3)*2;
            *reinterpret_cast<float2*>(&Cw[(size_t)r0*N + cc]) =
                make_float2(c[mt][nt][0], c[mt][nt][1]);
            *reinterpret_cast<float2*>(&Cw[(size_t)(r0+8)*N + cc]) =
                make_float2(c[mt][nt][2], c[mt][nt][3]);
        }
    }
}

// ---------------- split-K reduce ----------------------------------------------
__global__ void reduce_splitk(const float* __restrict__ part, const float* __restrict__ res,
                              float* __restrict__ out, int MN, int SK) {
    int i = blockIdx.x*256 + threadIdx.x;
    if (i >= MN) return;
    float s = res ? res[i] : 0.f;
    for (int k = 0; k < SK; k++) s += part[(size_t)k*MN + i];
    out[i] = s;
}

// ---------------- fused flash attention --------------------------------------
#define ATTN_SMEM (4*64*68*4 + 3*64*4)
__global__ void __launch_bounds__(256, 2) fattn(
    const float* __restrict__ Q, const float* __restrict__ Kg,
    const float* __restrict__ Vg, float* __restrict__ O,
    int lq, int lk, int ldk, int mask_mode, const unsigned char* __restrict__ kpm) {
    extern __shared__ float sm[];
    float (*Qs)[68] = (float(*)[68])sm;
    float (*Ks)[68] = (float(*)[68])(sm + 64*68);
    float (*Vs)[68] = (float(*)[68])(sm + 2*64*68);
    float (*Ps)[68] = (float(*)[68])(sm + 3*64*68);
    float* m_s  = sm + 4*64*68;
    float* l_s  = m_s + 64;
    float* al_s = l_s + 64;

    int tid = threadIdx.x;
    int q0 = blockIdx.x * 64;
    int bh = blockIdx.y;
    int b = bh >> 4, h = bh & 15;

#pragma unroll
    for (int i = 0; i < 4; i++) {
        int id = tid + i*256;
        int r = id >> 4, dq = (id & 15) * 4;
        *reinterpret_cast<float4*>(&Qs[r][dq]) =
            *reinterpret_cast<const float4*>(&Q[((size_t)(b*lq + q0 + r))*Ddim + h*HDdim + dq]);
    }
    if (tid < 64) { m_s[tid] = -INFINITY; l_s[tid] = 0.f; }
    __syncthreads();

    int ty = tid >> 4, tx = tid & 15;
    int r0 = ty * 4;
    float o[4][4] = {};

    int c_lo = 0, c_hi = lk >> 6;
    if (mask_mode) {
        c_lo = (q0 >= WINv) ? (q0 - WINv) >> 6 : 0;
        int hi = (q0 + 64 + WINv) >> 6;
        if (hi < c_hi) c_hi = hi;
    }

    for (int ck = c_lo; ck < c_hi; ck++) {
        int kb = ck * 64;
#pragma unroll
        for (int i = 0; i < 4; i++) {
            int id = tid + i*256;
            int r = id >> 4, dq = (id & 15)*4;
            size_t g = ((size_t)(b*lk + kb + r))*ldk + h*HDdim + dq;
            *reinterpret_cast<float4*>(&Ks[r][dq]) = *reinterpret_cast<const float4*>(&Kg[g]);
            *reinterpret_cast<float4*>(&Vs[r][dq]) = *reinterpret_cast<const float4*>(&Vg[g]);
        }
        __syncthreads();

        float s[4][4] = {};
#pragma unroll
        for (int k = 0; k < 64; k += 4) {
            float4 qv[4], kv[4];
#pragma unroll
            for (int i = 0; i < 4; i++) qv[i] = *reinterpret_cast<float4*>(&Qs[r0+i][k]);
#pragma unroll
            for (int j = 0; j < 4; j++) kv[j] = *reinterpret_cast<float4*>(&Ks[tx + 16*j][k]);
#pragma unroll
            for (int i = 0; i < 4; i++)
#pragma unroll
                for (int j = 0; j < 4; j++)
                    s[i][j] += qv[i].x*kv[j].x + qv[i].y*kv[j].y
                             + qv[i].z*kv[j].z + qv[i].w*kv[j].w;
        }
#pragma unroll
        for (int i = 0; i < 4; i++) {
            int qr = q0 + r0 + i;
#pragma unroll
            for (int j = 0; j < 4; j++) {
                int col = kb + tx + 16*j;
                float v = s[i][j] * 0.125f;
                int jr = col - qr;
                bool ok = true;
                if (mask_mode == 1) ok = (jr <= WINv && jr >= -WINv);
                else if (mask_mode == 2) ok = (jr <= WINv && jr >= -WINv && ((jr & 3) == 0));
                if (kpm && kpm[b*lk + col]) ok = false;
                Ps[r0+i][tx + 16*j] = ok ? v : -INFINITY;
            }
        }
        __syncthreads();

        {
            int w = tid >> 5, ln = tid & 31;
            for (int rr = w*8; rr < w*8 + 8; rr++) {
                float s0 = Ps[rr][ln], s1 = Ps[rr][ln+32];
                float mx = fmaxf(s0, s1);
#pragma unroll
                for (int off = 16; off; off >>= 1)
                    mx = fmaxf(mx, __shfl_xor_sync(0xffffffffu, mx, off));
                float mo = m_s[rr];
                float mn = fmaxf(mo, mx);
                float p0, p1, alpha;
                if (mn == -INFINITY) { p0 = 0.f; p1 = 0.f; alpha = 1.f; }
                else {
                    alpha = __expf(mo - mn);
                    p0 = (s0 == -INFINITY) ? 0.f : __expf(s0 - mn);
                    p1 = (s1 == -INFINITY) ? 0.f : __expf(s1 - mn);
                }
                Ps[rr][ln] = p0; Ps[rr][ln+32] = p1;
                float sum = p0 + p1;
#pragma unroll
                for (int off = 16; off; off >>= 1)
                    sum += __shfl_xor_sync(0xffffffffu, sum, off);
                if (ln == 0) {
                    l_s[rr] = l_s[rr]*alpha + sum;
                    m_s[rr] = mn;
                    al_s[rr] = alpha;
                }
            }
        }
        __syncthreads();

#pragma unroll
        for (int i = 0; i < 4; i++) {
            float a = al_s[r0+i];
#pragma unroll
            for (int j = 0; j < 4; j++) o[i][j] *= a;
        }
#pragma unroll
        for (int k = 0; k < 64; k += 4) {
            float4 pk[4];
#pragma unroll
            for (int i = 0; i < 4; i++) pk[i] = *reinterpret_cast<float4*>(&Ps[r0+i][k]);
#pragma unroll
            for (int kk = 0; kk < 4; kk++) {
                float4 vv = *reinterpret_cast<float4*>(&Vs[k+kk][tx*4]);
#pragma unroll
                for (int i = 0; i < 4; i++) {
                    float p = (kk == 0) ? pk[i].x : (kk == 1) ? pk[i].y : (kk == 2) ? pk[i].z : pk[i].w;
                    o[i][0] += p*vv.x; o[i][1] += p*vv.y; o[i][2] += p*vv.z; o[i][3] += p*vv.w;
                }
            }
        }
        __syncthreads();
    }

#pragma unroll
    for (int i = 0; i < 4; i++) {
        float inv = 1.0f / l_s[r0+i];
        float4 ov = make_float4(o[i][0]*inv, o[i][1]*inv, o[i][2]*inv, o[i][3]*inv);
        *reinterpret_cast<float4*>(&O[((size_t)(b*lq + q0 + r0 + i))*Ddim + h*HDdim + tx*4]) = ov;
    }
}

// ---------------- fused gate + residual + rmsnorm ----------------------------
__global__ void gate_fuse_norm(const float* __restrict__ x, const float* __restrict__ h,
                               const float* __restrict__ o0, const float* __restrict__ o1,
                               const float* __restrict__ o2, const float* __restrict__ o3,
                               const float* __restrict__ gw, const float* __restrict__ gb,
                               const float* __restrict__ nw,
                               float* __restrict__ x1, float* __restrict__ hn) {
    int row = blockIdx.x;
    int tid = threadIdx.x;          // 256
    int warp = tid >> 5, lane = tid & 31;
    __shared__ float wsh[4];
    __shared__ float red[8];
    size_t base = (size_t)row * Ddim;
    const float* hr = h + base;

    if (warp < 4) {
        float p = 0.f;
        const float* gwr = gw + warp * Ddim;
        for (int dd = lane; dd < Ddim; dd += 32) p += hr[dd] * gwr[dd];
#pragma unroll
        for (int off = 16; off; off >>= 1) p += __shfl_down_sync(0xffffffffu, p, off);
        if (lane == 0) wsh[warp] = p + gb[warp];
    }
    __syncthreads();
    if (tid == 0) {
        float mx = fmaxf(fmaxf(wsh[0], wsh[1]), fmaxf(wsh[2], wsh[3]));
        float e0 = expf(wsh[0]-mx), e1 = expf(wsh[1]-mx), e2 = expf(wsh[2]-mx), e3 = expf(wsh[3]-mx);
        float inv = 1.0f / (e0+e1+e2+e3);
        wsh[0] = e0*inv; wsh[1] = e1*inv; wsh[2] = e2*inv; wsh[3] = e3*inv;
    }
    __syncthreads();
    float w0 = wsh[0], w1 = wsh[1], w2 = wsh[2], w3 = wsh[3];

    float v[4];
    float ss = 0.f;
#pragma unroll
    for (int i = 0; i < 4; i++) {
        int dd = tid + i*256;
        float f = x[base+dd] + w0*o0[base+dd] + w1*o1[base+dd]
                             + w2*o2[base+dd] + w3*o3[base+dd];
        v[i] = f;
        ss += f*f;
        x1[base+dd] = f;
    }
#pragma unroll
    for (int off = 16; off; off >>= 1) ss += __shfl_xor_sync(0xffffffffu, ss, off);
    if (lane == 0) red[warp] = ss;
    __syncthreads();
    float tot = 0.f;
#pragma unroll
    for (int i = 0; i < 8; i++) tot += red[i];
    float scale = rsqrtf(tot * (1.0f/Ddim) + EPSV);
#pragma unroll
    for (int i = 0; i < 4; i++) {
        int dd = tid + i*256;
        hn[base+dd] = nw[dd] * (v[i] * scale);
    }
}

// ---------------- elementwise helpers ----------------------------------------
__global__ void broadcast_k(const float* __restrict__ src, float* __restrict__ dst,
                            int mask, int total) {
    int i = blockIdx.x*256 + threadIdx.x;
    if (i < total) dst[i] = src[i & mask];
}
__global__ void ema_k(const float* __restrict__ prev, const float* __restrict__ delta,
                      float* __restrict__ mem, int n) {
    int i = blockIdx.x*256 + threadIdx.x;
    if (i < n) mem[i] = 0.9f*prev[i] + 0.1f*(prev[i] + delta[i]);
}
// float4 silu*gate with fast exp
__global__ void silu_mul_k(const float* __restrict__ u, float* __restrict__ o, int n4) {
    int i = blockIdx.x*256 + threadIdx.x;
    if (i < n4) {
        int r = i >> 10;
        int f4 = i & 1023;
        const float4 a = *reinterpret_cast<const float4*>(&u[((size_t)r << 13) + f4*4]);
        const float4 g = *reinterpret_cast<const float4*>(&u[((size_t)r << 13) + DFFdim + f4*4]);
        float4 ov;
        ov.x = (a.x / (1.0f + __expf(-a.x))) * g.x;
        ov.y = (a.y / (1.0f + __expf(-a.y))) * g.y;
        ov.z = (a.z / (1.0f + __expf(-a.z))) * g.z;
        ov.w = (a.w / (1.0f + __expf(-a.w))) * g.w;
        *reinterpret_cast<float4*>(&o[(size_t)i*4]) = ov;
    }
}
__global__ void copy_k(const float* __restrict__ src, float* __restrict__ dst, int n) {
    int i = blockIdx.x*256 + threadIdx.x;
    if (i < n) dst[i] = src[i];
}

#define SYMF(name) ({ void* _p = nullptr; cudaGetSymbolAddress(&_p, name); (float*)_p; })

// generic projection: C[M,N] = A @ W^T (+res)
static void proj(const float* A, const float* W, const float* res, float* C,
                 float* partB, int M, int N, int K, cudaStream_t st) {
    if (M >= 1024) {
        gemm128<<<dim3(N/128, M/128, 1), 256, GEMM_SMEM, st>>>(A, W, res, C, M, N, K, K);
    } else {
        const int SK = 4;
        gemm64<<<dim3(N/64, M/64, SK), 128, 0, st>>>(A, W, partB, M, N, K, K/SK);
        int MN = M*N;
        reduce_splitk<<<(MN+255)/256, 256, 0, st>>>(partB, res, C, MN, SK);
    }
}

static void run_mha(const float* qin, const float* kvin, const float* w,
                    int lq, int lk, int mask_mode, const unsigned char* kpm,
                    const float* res, float* out,
                    float* Qb, float* KVb, float* Ob, float* partB, cudaStream_t st) {
    const float* Wq = w;
    const float* Wkv = w + Ddim*Ddim;
    const float* Wo = w + 3*Ddim*Ddim;
    int Mq = Bdim * lq, Mk = Bdim * lk;
    proj(qin, Wq, nullptr, Qb, partB, Mq, Ddim, Ddim, st);
    proj(kvin, Wkv, nullptr, KVb, partB, Mk, 2*Ddim, Ddim, st);
    fattn<<<dim3(lq/64, Bdim*Hdim), 256, ATTN_SMEM, st>>>(Qb, KVb, KVb + Ddim, Ob,
                                                          lq, lk, 2*Ddim, mask_mode, kpm);
    proj(Ob, Wo, res, out, partB, Mq, Ddim, Ddim, st);
}

extern "C" void kernel_launch(void* const* d_in, const int* in_sizes, int n_in,
                              void* d_out, int out_size) {
    const float* x          = (const float*)d_in[0];
    const unsigned char* kpm = (const unsigned char*)d_in[1];
    const float* norm_w     = (const float*)d_in[2];
    const float* ld_nq      = (const float*)d_in[3];
    const float* ld_nk      = (const float*)d_in[4];
    const float* local_w    = (const float*)d_in[5];
    const float* dil_w      = (const float*)d_in[6];
    const float* lat_tokens = (const float*)d_in[7];
    const float* lp_nq      = (const float*)d_in[8];
    const float* lp_nk      = (const float*)d_in[9];
    const float* lat_to_w   = (const float*)d_in[10];
    const float* lat_from_w = (const float*)d_in[11];
    const float* mem_tokens = (const float*)d_in[12];
    const float* mem_nq     = (const float*)d_in[13];
    const float* mem_nk     = (const float*)d_in[14];
    const float* mem_read_w = (const float*)d_in[15];
    const float* mem_write_w= (const float*)d_in[16];
    const float* gate_w     = (const float*)d_in[17];
    const float* gate_b     = (const float*)d_in[18];
    const float* up_w       = (const float*)d_in[19];
    const float* down_w     = (const float*)d_in[20];
    float* out = (float*)d_out;

    static cudaStream_t sA = nullptr, sB = nullptr;
    static cudaEvent_t evFork = nullptr, evA = nullptr, evB = nullptr;
    if (!sA) {
        cudaStreamCreateWithFlags(&sA, cudaStreamNonBlocking);
        cudaStreamCreateWithFlags(&sB, cudaStreamNonBlocking);
        cudaEventCreateWithFlags(&evFork, cudaEventDisableTiming);
        cudaEventCreateWithFlags(&evA, cudaEventDisableTiming);
        cudaEventCreateWithFlags(&evB, cudaEventDisableTiming);
        cudaFuncSetAttribute(fattn, cudaFuncAttributeMaxDynamicSharedMemorySize, ATTN_SMEM);
        cudaFuncSetAttribute(gemm128, cudaFuncAttributeMaxDynamicSharedMemorySize, GEMM_SMEM);
    }

    float* hB   = SYMF(g_h);
    float* qnB  = SYMF(g_qn);
    float* knB  = SYMF(g_kn);
    float* qn2B = SYMF(g_qn2);
    float* kn2B = SYMF(g_kn2);
    float* qn3B = SYMF(g_qn3);
    float* kn3B = SYMF(g_kn3);
    float* QaB  = SYMF(g_Qa);
    float* KVaB = SYMF(g_KVa);
    float* OaB  = SYMF(g_Oa);
    float* partaB = SYMF(g_parta);
    float* QbB  = SYMF(g_Qb);
    float* KVbB = SYMF(g_KVb);
    float* ObB  = SYMF(g_Ob);
    float* partbB = SYMF(g_partb);
    float* oLB  = SYMF(g_oL);
    float* oDB  = SYMF(g_oD);
    float* xlatB= SYMF(g_xlat);
    float* xmemB= SYMF(g_xmem);
    float* x1B  = SYMF(g_x1);
    float* hnB  = SYMF(g_hn);
    float* latprevB = SYMF(g_latprev);
    float* latB  = SYMF(g_lat);
    float* latqB = SYMF(g_latq);
    float* latkB = SYMF(g_latk);
    float* memprevB = SYMF(g_memprev);
    float* memB  = SYMF(g_mem);
    float* memqB = SYMF(g_memq);
    float* memkB = SYMF(g_memk);
    float* memdB = SYMF(g_memdelta);
    float* uB    = SYMF(g_u);
    float* gactB = SYMF(g_gact);

    const int rowsBL = Bdim * Ldim;

    // prologue: h, then ALL six norms of h in one pass
    rmsnorm_k<<<rowsBL, 256>>>(x, norm_w, hB);
    rmsnorm6_k<<<rowsBL, 256>>>(hB,
                                ld_nq, qnB,  ld_nk, knB,
                                lp_nk, kn2B, lp_nq, qn2B,
                                mem_nk, kn3B, mem_nq, qn3B);
    cudaEventRecord(evFork, 0);
    cudaStreamWaitEvent(sA, evFork, 0);
    cudaStreamWaitEvent(sB, evFork, 0);

    // ---- stream A: local branch, then latent chain ----
    run_mha(qnB, knB, local_w, Ldim, Ldim, 1, kpm, nullptr, oLB, QaB, KVaB, OaB, partaB, sA);

    broadcast_k<<<(BKD+255)/256, 256, 0, sA>>>(lat_tokens, latprevB, KLAT*Ddim - 1, BKD);
    rmsnorm_k<<<Bdim*KLAT, 256, 0, sA>>>(latprevB, lp_nq, latqB);
    run_mha(latqB, kn2B, lat_to_w, KLAT, Ldim, 0, kpm, latprevB, latB, QaB, KVaB, OaB, partaB, sA);
    rmsnorm_k<<<Bdim*KLAT, 256, 0, sA>>>(latB, lp_nk, latkB);
    run_mha(qn2B, latkB, lat_from_w, Ldim, KLAT, 0, nullptr, hB, xlatB, QaB, KVaB, OaB, partaB, sA);
    copy_k<<<(BKD+255)/256, 256, 0, sA>>>(latB, out + (size_t)BLD, BKD);
    cudaEventRecord(evA, sA);

    // ---- stream B: dilated branch, then memory chain ----
    run_mha(qnB, knB, dil_w, Ldim, Ldim, 2, kpm, nullptr, oDB, QbB, KVbB, ObB, partbB, sB);

    broadcast_k<<<(BMD+255)/256, 256, 0, sB>>>(mem_tokens, memprevB, MMEM*Ddim - 1, BMD);
    rmsnorm_k<<<Bdim*MMEM, 256, 0, sB>>>(memprevB, mem_nq, memqB);
    run_mha(memqB, kn3B, mem_write_w, MMEM, Ldim, 0, kpm, nullptr, memdB, QbB, KVbB, ObB, partbB, sB);
    ema_k<<<(BMD+255)/256, 256, 0, sB>>>(memprevB, memdB, memB, BMD);
    rmsnorm_k<<<Bdim*MMEM, 256, 0, sB>>>(memB, mem_nk, memkB);
    run_mha(qn3B, memkB, mem_read_w, Ldim, MMEM, 0, nullptr, hB, xmemB, QbB, KVbB, ObB, partbB, sB);
    copy_k<<<(BMD+255)/256, 256, 0, sB>>>(memB, out + (size_t)BLD + BKD, BMD);
    cudaEventRecord(evB, sB);

    // ---- join, then fused gate+norm + FFN on the capture stream ----
    cudaStreamWaitEvent(0, evA, 0);
    cudaStreamWaitEvent(0, evB, 0);

    gate_fuse_norm<<<rowsBL, 256>>>(x, hB, oLB, oDB, xlatB, xmemB,
                                    gate_w, gate_b, norm_w, x1B, hnB);

    gemm128<<<dim3(2*DFFdim/128, rowsBL/128, 1), 256, GEMM_SMEM>>>(hnB, up_w, nullptr, uB,
                                                        rowsBL, 2*DFFdim, Ddim, Ddim);
    int n4 = rowsBL * DFFdim / 4;
    silu_mul_k<<<(n4+255)/256, 256>>>(uB, gactB, n4);
    // down-proj split-K=2 (measured best: fills the solo capture stream)
    gemm128<<<dim3(Ddim/128, rowsBL/128, 2), 256, GEMM_SMEM>>>(gactB, down_w, nullptr, partaB,
                                                    rowsBL, Ddim, DFFdim, DFFdim/2);
    reduce_splitk<<<(BLD+255)/256, 256>>>(partaB, x1B, out, BLD, 2);
}

// round 17
// speedup vs baseline: 1.0265x; 1.0192x over previous
#include <cuda_runtime.h>
#include <math.h>
#include <stdint.h>

#define Bdim 2
#define Ldim 1024
#define Ddim 1024
#define Hdim 16
#define HDdim 64
#define DFFdim 4096
#define WINv 128
#define DILv 4
#define KLAT 64
#define MMEM 64
#define EPSV 1e-6f

#define BLD (Bdim*Ldim*Ddim)
#define BKD (Bdim*KLAT*Ddim)
#define BMD (Bdim*MMEM*Ddim)

// ---------------- scratch (static device memory; no allocations) -------------
__device__ float g_h[BLD];
__device__ float g_qn[BLD];
__device__ float g_kn[BLD];
__device__ float g_qn2[BLD];
__device__ float g_kn2[BLD];
__device__ float g_qn3[BLD];
__device__ float g_kn3[BLD];
__device__ float g_Qa[BLD];
__device__ float g_KVa[(size_t)Bdim*Ldim*2*Ddim];
__device__ float g_Oa[BLD];
__device__ float g_parta[(size_t)2048*1024*2];
__device__ float g_Qb[BLD];
__device__ float g_KVb[(size_t)Bdim*Ldim*2*Ddim];
__device__ float g_Ob[BLD];
__device__ float g_partb[(size_t)2048*1024*2];
__device__ float g_oL[BLD];
__device__ float g_oD[BLD];
__device__ float g_xlat[BLD];
__device__ float g_xmem[BLD];
__device__ float g_x1[BLD];
__device__ float g_hn[BLD];
__device__ float g_latprev[BKD];
__device__ float g_lat[BKD];
__device__ float g_latq[BKD];
__device__ float g_latk[BKD];
__device__ float g_memprev[BMD];
__device__ float g_mem[BMD];
__device__ float g_memq[BMD];
__device__ float g_memk[BMD];
__device__ float g_u[(size_t)Bdim*Ldim*2*DFFdim];
__device__ float g_gact[(size_t)Bdim*Ldim*DFFdim];

// ---------------- rmsnorm ----------------------------------------------------
__global__ void rmsnorm_k(const float* __restrict__ x, const float* __restrict__ w,
                          float* __restrict__ o) {
    int row = blockIdx.x;
    const float* xr = x + (size_t)row * Ddim;
    float* orow = o + (size_t)row * Ddim;
    int tid = threadIdx.x;          // 256 threads
    float v[4];
    float s = 0.f;
#pragma unroll
    for (int i = 0; i < 4; i++) { v[i] = xr[tid + i*256]; s += v[i]*v[i]; }
    __shared__ float red[8];
#pragma unroll
    for (int off = 16; off; off >>= 1) s += __shfl_xor_sync(0xffffffffu, s, off);
    if ((tid & 31) == 0) red[tid >> 5] = s;
    __syncthreads();
    float tot = 0.f;
#pragma unroll
    for (int i = 0; i < 8; i++) tot += red[i];
    float scale = rsqrtf(tot * (1.0f/Ddim) + EPSV);
#pragma unroll
    for (int i = 0; i < 4; i++) orow[tid + i*256] = w[tid + i*256] * (v[i] * scale);
}

// ---------------- rmsnorm of h with 6 weight vectors, one pass ---------------
__global__ void rmsnorm6_k(const float* __restrict__ h,
                           const float* __restrict__ w0, float* __restrict__ o0,
                           const float* __restrict__ w1, float* __restrict__ o1,
                           const float* __restrict__ w2, float* __restrict__ o2,
                           const float* __restrict__ w3, float* __restrict__ o3,
                           const float* __restrict__ w4, float* __restrict__ o4,
                           const float* __restrict__ w5, float* __restrict__ o5) {
    int row = blockIdx.x;
    size_t base = (size_t)row * Ddim;
    int tid = threadIdx.x;          // 256
    float v[4];
    float s = 0.f;
#pragma unroll
    for (int i = 0; i < 4; i++) { v[i] = h[base + tid + i*256]; s += v[i]*v[i]; }
    __shared__ float red[8];
#pragma unroll
    for (int off = 16; off; off >>= 1) s += __shfl_xor_sync(0xffffffffu, s, off);
    if ((tid & 31) == 0) red[tid >> 5] = s;
    __syncthreads();
    float tot = 0.f;
#pragma unroll
    for (int i = 0; i < 8; i++) tot += red[i];
    float scale = rsqrtf(tot * (1.0f/Ddim) + EPSV);
#pragma unroll
    for (int i = 0; i < 4; i++) {
        int dd = tid + i*256;
        float hv = v[i] * scale;
        o0[base+dd] = w0[dd] * hv;
        o1[base+dd] = w1[dd] * hv;
        o2[base+dd] = w2[dd] * hv;
        o3[base+dd] = w3[dd] * hv;
        o4[base+dd] = w4[dd] * hv;
        o5[base+dd] = w5[dd] * hv;
    }
}

// ---------------- tf32 mma helpers -------------------------------------------
__device__ __forceinline__ uint32_t f2tf(float f) {
    uint32_t u;
    asm("cvt.rna.tf32.f32 %0, %1;" : "=r"(u) : "f"(f));
    return u;
}
__device__ __forceinline__ void mma_tf32(float* c, const uint32_t* a, const uint32_t* b) {
    asm volatile("mma.sync.aligned.m16n8k8.row.col.f32.tf32.tf32.f32 "
        "{%0,%1,%2,%3}, {%4,%5,%6,%7}, {%8,%9}, {%0,%1,%2,%3};"
        : "+f"(c[0]), "+f"(c[1]), "+f"(c[2]), "+f"(c[3])
        : "r"(a[0]), "r"(a[1]), "r"(a[2]), "r"(a[3]), "r"(b[0]), "r"(b[1]));
}
__device__ __forceinline__ void ldsm4(uint32_t& r0, uint32_t& r1, uint32_t& r2, uint32_t& r3,
                                      uint32_t addr) {
    asm volatile("ldmatrix.sync.aligned.m8n8.x4.shared.b16 {%0,%1,%2,%3}, [%4];"
        : "=r"(r0), "=r"(r1), "=r"(r2), "=r"(r3) : "r"(addr));
}
__device__ __forceinline__ void cp16(uint32_t dst, const void* src) {
    asm volatile("cp.async.cg.shared.global [%0], [%1], 16;" :: "r"(dst), "l"(src));
}
__device__ __forceinline__ void cp_commit() {
    asm volatile("cp.async.commit_group;");
}
template <int N>
__device__ __forceinline__ void cp_wait() {
    asm volatile("cp.async.wait_group %0;" :: "n"(N));
}

// ---------------- GEMM 128x128, 256 thr, cp.async 4-stage, ldmatrix ----------
#define GSTAGE 4
#define GTILEF (128*20)
#define GEMM_SMEM (GSTAGE*GTILEF*2*4)
__global__ void __launch_bounds__(256, 2) gemm128(
    const float* __restrict__ A, const float* __restrict__ Bm,
    const float* __restrict__ res, float* __restrict__ C,
    int M, int N, int K, int Kc) {
    extern __shared__ float smg[];
    float* As = smg;
    float* Bs = smg + GSTAGE*GTILEF;
    int tid = threadIdx.x, lane = tid & 31, wid = tid >> 5;
    int bm = blockIdx.y * 128, bn = blockIdx.x * 128;
    int wm = (wid & 1) * 64, wn = (wid >> 1) * 32;
    int k0base = blockIdx.z * Kc;
    float* Cw = C + (size_t)blockIdx.z * M * N;

    int lrow = tid >> 1;
    int lkq  = (tid & 1) * 8;
    const float* Ag = A + (size_t)(bm + lrow) * K + k0base + lkq;
    const float* Bg = Bm + (size_t)(bn + lrow) * K + k0base + lkq;
    uint32_t sA = (uint32_t)__cvta_generic_to_shared(As) + (lrow*20 + lkq)*4;
    uint32_t sB = (uint32_t)__cvta_generic_to_shared(Bs) + (lrow*20 + lkq)*4;

    int rowA = (lane & 7) + ((lane >> 3) & 1) * 8;
    int kA   = (lane >> 4) * 4;
    int rowB = (lane & 7) + (lane >> 4) * 8;
    int kB   = ((lane >> 3) & 1) * 4;
    uint32_t aLd = (uint32_t)__cvta_generic_to_shared(As) + ((wm + rowA)*20 + kA)*4;
    uint32_t bLd = (uint32_t)__cvta_generic_to_shared(Bs) + ((wn + rowB)*20 + kB)*4;

    float c[4][4][4] = {};
    int ntiles = Kc >> 4;

#pragma unroll
    for (int s = 0; s < 3; s++) {
        if (s < ntiles) {
            const float* Ap = Ag + (size_t)s*16;
            const float* Bp = Bg + (size_t)s*16;
            uint32_t aOff = sA + s*GTILEF*4;
            uint32_t bOff = sB + s*GTILEF*4;
            cp16(aOff, Ap); cp16(aOff + 16, Ap + 4);
            cp16(bOff, Bp); cp16(bOff + 16, Bp + 4);
        }
        cp_commit();
    }

    for (int kt = 0; kt < ntiles; kt++) {
        cp_wait<2>();
        __syncthreads();
        if (kt + 3 < ntiles) {
            int s = (kt + 3) % GSTAGE;
            const float* Ap = Ag + (size_t)(kt+3)*16;
            const float* Bp = Bg + (size_t)(kt+3)*16;
            cp16(sA + s*GTILEF*4, Ap); cp16(sA + s*GTILEF*4 + 16, Ap + 4);
            cp16(sB + s*GTILEF*4, Bp); cp16(sB + s*GTILEF*4 + 16, Bp + 4);
        }
        cp_commit();

        uint32_t stOff = (uint32_t)(kt % GSTAGE) * GTILEF * 4;
#pragma unroll
        for (int ks = 0; ks < 2; ks++) {
            uint32_t ksOff = stOff + ks * 32;
            uint32_t a[4][4], b[4][2];
#pragma unroll
            for (int mt = 0; mt < 4; mt++)
                ldsm4(a[mt][0], a[mt][1], a[mt][2], a[mt][3],
                      aLd + ksOff + mt * 1280);
            ldsm4(b[0][0], b[0][1], b[1][0], b[1][1], bLd + ksOff);
            ldsm4(b[2][0], b[2][1], b[3][0], b[3][1], bLd + ksOff + 1280);
#pragma unroll
            for (int mt = 0; mt < 4; mt++)
#pragma unroll
                for (int nt = 0; nt < 4; nt++)
                    mma_tf32(c[mt][nt], a[mt], b[nt]);
        }
    }

#pragma unroll
    for (int mt = 0; mt < 4; mt++) {
        int r0 = bm + wm + mt*16 + (lane >> 2);
#pragma unroll
        for (int nt = 0; nt < 4; nt++) {
            int cc = bn + wn + nt*8 + (lane & 3)*2;
            float2 v0 = make_float2(c[mt][nt][0], c[mt][nt][1]);
            float2 v1 = make_float2(c[mt][nt][2], c[mt][nt][3]);
            if (res) {
                float2 q0 = *reinterpret_cast<const float2*>(&res[(size_t)r0*N + cc]);
                float2 q1 = *reinterpret_cast<const float2*>(&res[(size_t)(r0+8)*N + cc]);
                v0.x += q0.x; v0.y += q0.y; v1.x += q1.x; v1.y += q1.y;
            }
            *reinterpret_cast<float2*>(&Cw[(size_t)r0*N + cc]) = v0;
            *reinterpret_cast<float2*>(&Cw[(size_t)(r0+8)*N + cc]) = v1;
        }
    }
}

// ---------------- GEMM 64x64, 128 thr, split-K (small M) ---------------------
__global__ void __launch_bounds__(128, 4) gemm64(
    const float* __restrict__ A, const float* __restrict__ Bm,
    float* __restrict__ C, int M, int N, int K, int Kc) {
    __shared__ uint32_t As[2][64][20];
    __shared__ uint32_t Bs[2][64][20];
    int tid = threadIdx.x, lane = tid & 31, wid = tid >> 5;
    int bm = blockIdx.y * 64, bn = blockIdx.x * 64;
    int wm = (wid & 1) * 32, wn = (wid >> 1) * 32;
    int k0base = blockIdx.z * Kc;
    float* Cw = C + (size_t)blockIdx.z * M * N;

    int lrow = tid >> 1;
    int lkq  = (tid & 1) * 8;
    const float* Ag = A + (size_t)(bm + lrow) * K + k0base + lkq;
    const float* Bg = Bm + (size_t)(bn + lrow) * K + k0base + lkq;

    float c[2][4][4] = {};
    int ntiles = Kc >> 4;

    float4 la0, la1, lb0, lb1;
    la0 = *reinterpret_cast<const float4*>(Ag);
    la1 = *reinterpret_cast<const float4*>(Ag + 4);
    lb0 = *reinterpret_cast<const float4*>(Bg);
    lb1 = *reinterpret_cast<const float4*>(Bg + 4);
    As[0][lrow][lkq+0] = f2tf(la0.x); As[0][lrow][lkq+1] = f2tf(la0.y);
    As[0][lrow][lkq+2] = f2tf(la0.z); As[0][lrow][lkq+3] = f2tf(la0.w);
    As[0][lrow][lkq+4] = f2tf(la1.x); As[0][lrow][lkq+5] = f2tf(la1.y);
    As[0][lrow][lkq+6] = f2tf(la1.z); As[0][lrow][lkq+7] = f2tf(la1.w);
    Bs[0][lrow][lkq+0] = f2tf(lb0.x); Bs[0][lrow][lkq+1] = f2tf(lb0.y);
    Bs[0][lrow][lkq+2] = f2tf(lb0.z); Bs[0][lrow][lkq+3] = f2tf(lb0.w);
    Bs[0][lrow][lkq+4] = f2tf(lb1.x); Bs[0][lrow][lkq+5] = f2tf(lb1.y);
    Bs[0][lrow][lkq+6] = f2tf(lb1.z); Bs[0][lrow][lkq+7] = f2tf(lb1.w);
    __syncthreads();

    for (int kt = 0; kt < ntiles; kt++) {
        int cur = kt & 1;
        if (kt + 1 < ntiles) {
            const float* Ap = Ag + (size_t)(kt+1)*16;
            const float* Bp = Bg + (size_t)(kt+1)*16;
            la0 = *reinterpret_cast<const float4*>(Ap);
            la1 = *reinterpret_cast<const float4*>(Ap + 4);
            lb0 = *reinterpret_cast<const float4*>(Bp);
            lb1 = *reinterpret_cast<const float4*>(Bp + 4);
        }
#pragma unroll
        for (int ks = 0; ks < 2; ks++) {
            int kb = ks*8 + (lane & 3);
            int rA = wm + (lane >> 2);
            int rB = wn + (lane >> 2);
            uint32_t a[2][4], b[4][2];
#pragma unroll
            for (int mt = 0; mt < 2; mt++) {
                a[mt][0] = As[cur][rA + mt*16    ][kb];
                a[mt][1] = As[cur][rA + mt*16 + 8][kb];
                a[mt][2] = As[cur][rA + mt*16    ][kb+4];
                a[mt][3] = As[cur][rA + mt*16 + 8][kb+4];
            }
#pragma unroll
            for (int nt = 0; nt < 4; nt++) {
                b[nt][0] = Bs[cur][rB + nt*8][kb];
                b[nt][1] = Bs[cur][rB + nt*8][kb+4];
            }
#pragma unroll
            for (int mt = 0; mt < 2; mt++)
#pragma unroll
                for (int nt = 0; nt < 4; nt++)
                    mma_tf32(c[mt][nt], a[mt], b[nt]);
        }
        if (kt + 1 < ntiles) {
            int nxt = cur ^ 1;
            As[nxt][lrow][lkq+0] = f2tf(la0.x); As[nxt][lrow][lkq+1] = f2tf(la0.y);
            As[nxt][lrow][lkq+2] = f2tf(la0.z); As[nxt][lrow][lkq+3] = f2tf(la0.w);
            As[nxt][lrow][lkq+4] = f2tf(la1.x); As[nxt][lrow][lkq+5] = f2tf(la1.y);
            As[nxt][lrow][lkq+6] = f2tf(la1.z); As[nxt][lrow][lkq+7] = f2tf(la1.w);
            Bs[nxt][lrow][lkq+0] = f2tf(lb0.x); Bs[nxt][lrow][lkq+1] = f2tf(lb0.y);
            Bs[nxt][lrow][lkq+2] = f2tf(lb0.z); Bs[nxt][lrow][lkq+3] = f2tf(lb0.w);
            Bs[nxt][lrow][lkq+4] = f2tf(lb1.x); Bs[nxt][lrow][lkq+5] = f2tf(lb1.y);
            Bs[nxt][lrow][lkq+6] = f2tf(lb1.z); Bs[nxt][lrow][lkq+7] = f2tf(lb1.w);
        }
        __syncthreads();
    }

#pragma unroll
    for (int mt = 0; mt < 2; mt++) {
        int r0 = bm + wm + mt*16 + (lane >> 2);
#pragma unroll
        for (int nt = 0; nt < 4; nt++) {
            int cc = bn + wn + nt*8 + (lane & 3)*2;
            *reinterpret_cast<float2*>(&Cw[(size_t)r0*N + cc]) =
                make_float2(c[mt][nt][0], c[mt][nt][1]);
            *reinterpret_cast<float2*>(&Cw[(size_t)(r0+8)*N + cc]) =
                make_float2(c[mt][nt][2], c[mt][nt][3]);
        }
    }
}

// ---------------- split-K reduce with scale: out = res + alpha*sum ------------
__global__ void reduce_splitk(const float* __restrict__ part, const float* __restrict__ res,
                              float* __restrict__ out, int MN, int SK, float alpha) {
    int i = blockIdx.x*256 + threadIdx.x;
    if (i >= MN) return;
    float s = 0.f;
    for (int k = 0; k < SK; k++) s += part[(size_t)k*MN + i];
    out[i] = (res ? res[i] : 0.f) + alpha * s;
}

// ---------------- fused flash attention --------------------------------------
#define ATTN_SMEM (4*64*68*4 + 3*64*4)
__global__ void __launch_bounds__(256, 2) fattn(
    const float* __restrict__ Q, const float* __restrict__ Kg,
    const float* __restrict__ Vg, float* __restrict__ O,
    int lq, int lk, int ldk, int mask_mode, const unsigned char* __restrict__ kpm) {
    extern __shared__ float sm[];
    float (*Qs)[68] = (float(*)[68])sm;
    float (*Ks)[68] = (float(*)[68])(sm + 64*68);
    float (*Vs)[68] = (float(*)[68])(sm + 2*64*68);
    float (*Ps)[68] = (float(*)[68])(sm + 3*64*68);
    float* m_s  = sm + 4*64*68;
    float* l_s  = m_s + 64;
    float* al_s = l_s + 64;

    int tid = threadIdx.x;
    int q0 = blockIdx.x * 64;
    int bh = blockIdx.y;
    int b = bh >> 4, h = bh & 15;

#pragma unroll
    for (int i = 0; i < 4; i++) {
        int id = tid + i*256;
        int r = id >> 4, dq = (id & 15) * 4;
        *reinterpret_cast<float4*>(&Qs[r][dq]) =
            *reinterpret_cast<const float4*>(&Q[((size_t)(b*lq + q0 + r))*Ddim + h*HDdim + dq]);
    }
    if (tid < 64) { m_s[tid] = -INFINITY; l_s[tid] = 0.f; }
    __syncthreads();

    int ty = tid >> 4, tx = tid & 15;
    int r0 = ty * 4;
    float o[4][4] = {};

    int c_lo = 0, c_hi = lk >> 6;
    if (mask_mode) {
        c_lo = (q0 >= WINv) ? (q0 - WINv) >> 6 : 0;
        int hi = (q0 + 64 + WINv) >> 6;
        if (hi < c_hi) c_hi = hi;
    }

    for (int ck = c_lo; ck < c_hi; ck++) {
        int kb = ck * 64;
#pragma unroll
        for (int i = 0; i < 4; i++) {
            int id = tid + i*256;
            int r = id >> 4, dq = (id & 15)*4;
            size_t g = ((size_t)(b*lk + kb + r))*ldk + h*HDdim + dq;
            *reinterpret_cast<float4*>(&Ks[r][dq]) = *reinterpret_cast<const float4*>(&Kg[g]);
            *reinterpret_cast<float4*>(&Vs[r][dq]) = *reinterpret_cast<const float4*>(&Vg[g]);
        }
        __syncthreads();

        float s[4][4] = {};
#pragma unroll
        for (int k = 0; k < 64; k += 4) {
            float4 qv[4], kv[4];
#pragma unroll
            for (int i = 0; i < 4; i++) qv[i] = *reinterpret_cast<float4*>(&Qs[r0+i][k]);
#pragma unroll
            for (int j = 0; j < 4; j++) kv[j] = *reinterpret_cast<float4*>(&Ks[tx + 16*j][k]);
#pragma unroll
            for (int i = 0; i < 4; i++)
#pragma unroll
                for (int j = 0; j < 4; j++)
                    s[i][j] += qv[i].x*kv[j].x + qv[i].y*kv[j].y
                             + qv[i].z*kv[j].z + qv[i].w*kv[j].w;
        }
#pragma unroll
        for (int i = 0; i < 4; i++) {
            int qr = q0 + r0 + i;
#pragma unroll
            for (int j = 0; j < 4; j++) {
                int col = kb + tx + 16*j;
                float v = s[i][j] * 0.125f;
                int jr = col - qr;
                bool ok = true;
                if (mask_mode == 1) ok = (jr <= WINv && jr >= -WINv);
                else if (mask_mode == 2) ok = (jr <= WINv && jr >= -WINv && ((jr & 3) == 0));
                if (kpm && kpm[b*lk + col]) ok = false;
                Ps[r0+i][tx + 16*j] = ok ? v : -INFINITY;
            }
        }
        __syncthreads();

        {
            int w = tid >> 5, ln = tid & 31;
            for (int rr = w*8; rr < w*8 + 8; rr++) {
                float s0 = Ps[rr][ln], s1 = Ps[rr][ln+32];
                float mx = fmaxf(s0, s1);
#pragma unroll
                for (int off = 16; off; off >>= 1)
                    mx = fmaxf(mx, __shfl_xor_sync(0xffffffffu, mx, off));
                float mo = m_s[rr];
                float mn = fmaxf(mo, mx);
                float p0, p1, alpha;
                if (mn == -INFINITY) { p0 = 0.f; p1 = 0.f; alpha = 1.f; }
                else {
                    alpha = __expf(mo - mn);
                    p0 = (s0 == -INFINITY) ? 0.f : __expf(s0 - mn);
                    p1 = (s1 == -INFINITY) ? 0.f : __expf(s1 - mn);
                }
                Ps[rr][ln] = p0; Ps[rr][ln+32] = p1;
                float sum = p0 + p1;
#pragma unroll
                for (int off = 16; off; off >>= 1)
                    sum += __shfl_xor_sync(0xffffffffu, sum, off);
                if (ln == 0) {
                    l_s[rr] = l_s[rr]*alpha + sum;
                    m_s[rr] = mn;
                    al_s[rr] = alpha;
                }
            }
        }
        __syncthreads();

#pragma unroll
        for (int i = 0; i < 4; i++) {
            float a = al_s[r0+i];
#pragma unroll
            for (int j = 0; j < 4; j++) o[i][j] *= a;
        }
#pragma unroll
        for (int k = 0; k < 64; k += 4) {
            float4 pk[4];
#pragma unroll
            for (int i = 0; i < 4; i++) pk[i] = *reinterpret_cast<float4*>(&Ps[r0+i][k]);
#pragma unroll
            for (int kk = 0; kk < 4; kk++) {
                float4 vv = *reinterpret_cast<float4*>(&Vs[k+kk][tx*4]);
#pragma unroll
                for (int i = 0; i < 4; i++) {
                    float p = (kk == 0) ? pk[i].x : (kk == 1) ? pk[i].y : (kk == 2) ? pk[i].z : pk[i].w;
                    o[i][0] += p*vv.x; o[i][1] += p*vv.y; o[i][2] += p*vv.z; o[i][3] += p*vv.w;
                }
            }
        }
        __syncthreads();
    }

#pragma unroll
    for (int i = 0; i < 4; i++) {
        float inv = 1.0f / l_s[r0+i];
        float4 ov = make_float4(o[i][0]*inv, o[i][1]*inv, o[i][2]*inv, o[i][3]*inv);
        *reinterpret_cast<float4*>(&O[((size_t)(b*lq + q0 + r0 + i))*Ddim + h*HDdim + tx*4]) = ov;
    }
}

// ---------------- dilated flash attention (residue decomposition) ------------
// q = 4u+r attends exactly cols 4v+r with |v-u| <= WINv/DILv (=32).
// Grid: (lq/4/64 u-tiles, B*H*4). Dense band over subsampled seq of len lq/4.
__global__ void __launch_bounds__(256, 2) fattn_dil(
    const float* __restrict__ Q, const float* __restrict__ Kg,
    const float* __restrict__ Vg, float* __restrict__ O,
    int lq, int ldk, const unsigned char* __restrict__ kpm) {
    extern __shared__ float sm[];
    float (*Qs)[68] = (float(*)[68])sm;
    float (*Ks)[68] = (float(*)[68])(sm + 64*68);
    float (*Vs)[68] = (float(*)[68])(sm + 2*64*68);
    float (*Ps)[68] = (float(*)[68])(sm + 3*64*68);
    float* m_s  = sm + 4*64*68;
    float* l_s  = m_s + 64;
    float* al_s = l_s + 64;

    const int LU = Ldim / DILv;     // 256 subsampled length
    const int WU = WINv / DILv;     // 32 subsampled window

    int tid = threadIdx.x;
    int u0 = blockIdx.x * 64;
    int bhr = blockIdx.y;
    int rres = bhr & 3;
    int h = (bhr >> 2) & 15;
    int b = bhr >> 6;

#pragma unroll
    for (int i = 0; i < 4; i++) {
        int id = tid + i*256;
        int rr = id >> 4, dq = (id & 15) * 4;
        int qrow = 4*(u0 + rr) + rres;
        *reinterpret_cast<float4*>(&Qs[rr][dq]) =
            *reinterpret_cast<const float4*>(&Q[((size_t)(b*lq + qrow))*Ddim + h*HDdim + dq]);
    }
    if (tid < 64) { m_s[tid] = -INFINITY; l_s[tid] = 0.f; }
    __syncthreads();

    int ty = tid >> 4, tx = tid & 15;
    int r0 = ty * 4;
    float o[4][4] = {};

    int c_lo = (u0 >= WU) ? (u0 - WU) >> 6 : 0;
    int c_hi = (u0 + 64 + WU + 63) >> 6;
    int cmax = LU >> 6;
    if (c_hi > cmax) c_hi = cmax;

    for (int ck = c_lo; ck < c_hi; ck++) {
        int kb = ck * 64;
#pragma unroll
        for (int i = 0; i < 4; i++) {
            int id = tid + i*256;
            int rr = id >> 4, dq = (id & 15)*4;
            int krow = 4*(kb + rr) + rres;
            size_t g = ((size_t)(b*lq + krow))*ldk + h*HDdim + dq;
            *reinterpret_cast<float4*>(&Ks[rr][dq]) = *reinterpret_cast<const float4*>(&Kg[g]);
            *reinterpret_cast<float4*>(&Vs[rr][dq]) = *reinterpret_cast<const float4*>(&Vg[g]);
        }
        __syncthreads();

        float s[4][4] = {};
#pragma unroll
        for (int k = 0; k < 64; k += 4) {
            float4 qv[4], kv[4];
#pragma unroll
            for (int i = 0; i < 4; i++) qv[i] = *reinterpret_cast<float4*>(&Qs[r0+i][k]);
#pragma unroll
            for (int j = 0; j < 4; j++) kv[j] = *reinterpret_cast<float4*>(&Ks[tx + 16*j][k]);
#pragma unroll
            for (int i = 0; i < 4; i++)
#pragma unroll
                for (int j = 0; j < 4; j++)
                    s[i][j] += qv[i].x*kv[j].x + qv[i].y*kv[j].y
                             + qv[i].z*kv[j].z + qv[i].w*kv[j].w;
        }
#pragma unroll
        for (int i = 0; i < 4; i++) {
            int uq = u0 + r0 + i;
#pragma unroll
            for (int j = 0; j < 4; j++) {
                int vcol = kb + tx + 16*j;
                float v = s[i][j] * 0.125f;
                int dv = vcol - uq;
                bool ok = (dv <= WU && dv >= -WU);
                if (kpm && kpm[b*lq + 4*vcol + rres]) ok = false;
                Ps[r0+i][tx + 16*j] = ok ? v : -INFINITY;
            }
        }
        __syncthreads();

        {
            int w = tid >> 5, ln = tid & 31;
            for (int rr = w*8; rr < w*8 + 8; rr++) {
                float s0 = Ps[rr][ln], s1 = Ps[rr][ln+32];
                float mx = fmaxf(s0, s1);
#pragma unroll
                for (int off = 16; off; off >>= 1)
                    mx = fmaxf(mx, __shfl_xor_sync(0xffffffffu, mx, off));
                float mo = m_s[rr];
                float mn = fmaxf(mo, mx);
                float p0, p1, alpha;
                if (mn == -INFINITY) { p0 = 0.f; p1 = 0.f; alpha = 1.f; }
                else {
                    alpha = __expf(mo - mn);
                    p0 = (s0 == -INFINITY) ? 0.f : __expf(s0 - mn);
                    p1 = (s1 == -INFINITY) ? 0.f : __expf(s1 - mn);
                }
                Ps[rr][ln] = p0; Ps[rr][ln+32] = p1;
                float sum = p0 + p1;
#pragma unroll
                for (int off = 16; off; off >>= 1)
                    sum += __shfl_xor_sync(0xffffffffu, sum, off);
                if (ln == 0) {
                    l_s[rr] = l_s[rr]*alpha + sum;
                    m_s[rr] = mn;
                    al_s[rr] = alpha;
                }
            }
        }
        __syncthreads();

#pragma unroll
        for (int i = 0; i < 4; i++) {
            float a = al_s[r0+i];
#pragma unroll
            for (int j = 0; j < 4; j++) o[i][j] *= a;
        }
#pragma unroll
        for (int k = 0; k < 64; k += 4) {
            float4 pk[4];
#pragma unroll
            for (int i = 0; i < 4; i++) pk[i] = *reinterpret_cast<float4*>(&Ps[r0+i][k]);
#pragma unroll
            for (int kk = 0; kk < 4; kk++) {
                float4 vv = *reinterpret_cast<float4*>(&Vs[k+kk][tx*4]);
#pragma unroll
                for (int i = 0; i < 4; i++) {
                    float p = (kk == 0) ? pk[i].x : (kk == 1) ? pk[i].y : (kk == 2) ? pk[i].z : pk[i].w;
                    o[i][0] += p*vv.x; o[i][1] += p*vv.y; o[i][2] += p*vv.z; o[i][3] += p*vv.w;
                }
            }
        }
        __syncthreads();
    }

#pragma unroll
    for (int i = 0; i < 4; i++) {
        float inv = 1.0f / l_s[r0+i];
        int qrow = 4*(u0 + r0 + i) + rres;
        float4 ov = make_float4(o[i][0]*inv, o[i][1]*inv, o[i][2]*inv, o[i][3]*inv);
        *reinterpret_cast<float4*>(&O[((size_t)(b*lq + qrow))*Ddim + h*HDdim + tx*4]) = ov;
    }
}

// ---------------- fused gate + residual + rmsnorm ----------------------------
__global__ void gate_fuse_norm(const float* __restrict__ x, const float* __restrict__ h,
                               const float* __restrict__ o0, const float* __restrict__ o1,
                               const float* __restrict__ o2, const float* __restrict__ o3,
                               const float* __restrict__ gw, const float* __restrict__ gb,
                               const float* __restrict__ nw,
                               float* __restrict__ x1, float* __restrict__ hn) {
    int row = blockIdx.x;
    int tid = threadIdx.x;
    int warp = tid >> 5, lane = tid & 31;
    __shared__ float wsh[4];
    __shared__ float red[8];
    size_t base = (size_t)row * Ddim;
    const float* hr = h + base;

    if (warp < 4) {
        float p = 0.f;
        const float* gwr = gw + warp * Ddim;
        for (int dd = lane; dd < Ddim; dd += 32) p += hr[dd] * gwr[dd];
#pragma unroll
        for (int off = 16; off; off >>= 1) p += __shfl_down_sync(0xffffffffu, p, off);
        if (lane == 0) wsh[warp] = p + gb[warp];
    }
    __syncthreads();
    if (tid == 0) {
        float mx = fmaxf(fmaxf(wsh[0], wsh[1]), fmaxf(wsh[2], wsh[3]));
        float e0 = expf(wsh[0]-mx), e1 = expf(wsh[1]-mx), e2 = expf(wsh[2]-mx), e3 = expf(wsh[3]-mx);
        float inv = 1.0f / (e0+e1+e2+e3);
        wsh[0] = e0*inv; wsh[1] = e1*inv; wsh[2] = e2*inv; wsh[3] = e3*inv;
    }
    __syncthreads();
    float w0 = wsh[0], w1 = wsh[1], w2 = wsh[2], w3 = wsh[3];

    float v[4];
    float ss = 0.f;
#pragma unroll
    for (int i = 0; i < 4; i++) {
        int dd = tid + i*256;
        float f = x[base+dd] + w0*o0[base+dd] + w1*o1[base+dd]
                             + w2*o2[base+dd] + w3*o3[base+dd];
        v[i] = f;
        ss += f*f;
        x1[base+dd] = f;
    }
#pragma unroll
    for (int off = 16; off; off >>= 1) ss += __shfl_xor_sync(0xffffffffu, ss, off);
    if (lane == 0) red[warp] = ss;
    __syncthreads();
    float tot = 0.f;
#pragma unroll
    for (int i = 0; i < 8; i++) tot += red[i];
    float scale = rsqrtf(tot * (1.0f/Ddim) + EPSV);
#pragma unroll
    for (int i = 0; i < 4; i++) {
        int dd = tid + i*256;
        hn[base+dd] = nw[dd] * (v[i] * scale);
    }
}

// ---------------- elementwise helpers ----------------------------------------
__global__ void broadcast_k(const float* __restrict__ src, float* __restrict__ dst,
                            int mask, int total) {
    int i = blockIdx.x*256 + threadIdx.x;
    if (i < total) dst[i] = src[i & mask];
}
__global__ void silu_mul_k(const float* __restrict__ u, float* __restrict__ o, int n4) {
    int i = blockIdx.x*256 + threadIdx.x;
    if (i < n4) {
        int r = i >> 10;
        int f4 = i & 1023;
        const float4 a = *reinterpret_cast<const float4*>(&u[((size_t)r << 13) + f4*4]);
        const float4 g = *reinterpret_cast<const float4*>(&u[((size_t)r << 13) + DFFdim + f4*4]);
        float4 ov;
        ov.x = (a.x / (1.0f + __expf(-a.x))) * g.x;
        ov.y = (a.y / (1.0f + __expf(-a.y))) * g.y;
        ov.z = (a.z / (1.0f + __expf(-a.z))) * g.z;
        ov.w = (a.w / (1.0f + __expf(-a.w))) * g.w;
        *reinterpret_cast<float4*>(&o[(size_t)i*4]) = ov;
    }
}
__global__ void copy_k(const float* __restrict__ src, float* __restrict__ dst, int n) {
    int i = blockIdx.x*256 + threadIdx.x;
    if (i < n) dst[i] = src[i];
}

#define SYMF(name) ({ void* _p = nullptr; cudaGetSymbolAddress(&_p, name); (float*)_p; })

// generic projection: C[M,N] = alpha * (A @ W^T) + res
static void proj(const float* A, const float* W, const float* res, float* C,
                 float* partB, int M, int N, int K, cudaStream_t st, float alpha = 1.f) {
    if (M >= 1024) {
        // alpha always 1 on this path
        gemm128<<<dim3(N/128, M/128, 1), 256, GEMM_SMEM, st>>>(A, W, res, C, M, N, K, K);
    } else {
        const int SK = 4;
        gemm64<<<dim3(N/64, M/64, SK), 128, 0, st>>>(A, W, partB, M, N, K, K/SK);
        int MN = M*N;
        reduce_splitk<<<(MN+255)/256, 256, 0, st>>>(partB, res, C, MN, SK, alpha);
    }
}

static void run_mha(const float* qin, const float* kvin, const float* w,
                    int lq, int lk, int mask_mode, const unsigned char* kpm,
                    const float* res, float* out,
                    float* Qb, float* KVb, float* Ob, float* partB, cudaStream_t st,
                    float out_alpha = 1.f) {
    const float* Wq = w;
    const float* Wkv = w + Ddim*Ddim;
    const float* Wo = w + 3*Ddim*Ddim;
    int Mq = Bdim * lq, Mk = Bdim * lk;
    proj(qin, Wq, nullptr, Qb, partB, Mq, Ddim, Ddim, st);
    proj(kvin, Wkv, nullptr, KVb, partB, Mk, 2*Ddim, Ddim, st);
    if (mask_mode == 2) {
        fattn_dil<<<dim3(Ldim/DILv/64, Bdim*Hdim*DILv), 256, ATTN_SMEM, st>>>(
            Qb, KVb, KVb + Ddim, Ob, lq, 2*Ddim, kpm);
    } else {
        fattn<<<dim3(lq/64, Bdim*Hdim), 256, ATTN_SMEM, st>>>(Qb, KVb, KVb + Ddim, Ob,
                                                              lq, lk, 2*Ddim, mask_mode, kpm);
    }
    proj(Ob, Wo, res, out, partB, Mq, Ddim, Ddim, st, out_alpha);
}

extern "C" void kernel_launch(void* const* d_in, const int* in_sizes, int n_in,
                              void* d_out, int out_size) {
    const float* x          = (const float*)d_in[0];
    const unsigned char* kpm = (const unsigned char*)d_in[1];
    const float* norm_w     = (const float*)d_in[2];
    const float* ld_nq      = (const float*)d_in[3];
    const float* ld_nk      = (const float*)d_in[4];
    const float* local_w    = (const float*)d_in[5];
    const float* dil_w      = (const float*)d_in[6];
    const float* lat_tokens = (const float*)d_in[7];
    const float* lp_nq      = (const float*)d_in[8];
    const float* lp_nk      = (const float*)d_in[9];
    const float* lat_to_w   = (const float*)d_in[10];
    const float* lat_from_w = (const float*)d_in[11];
    const float* mem_tokens = (const float*)d_in[12];
    const float* mem_nq     = (const float*)d_in[13];
    const float* mem_nk     = (const float*)d_in[14];
    const float* mem_read_w = (const float*)d_in[15];
    const float* mem_write_w= (const float*)d_in[16];
    const float* gate_w     = (const float*)d_in[17];
    const float* gate_b     = (const float*)d_in[18];
    const float* up_w       = (const float*)d_in[19];
    const float* down_w     = (const float*)d_in[20];
    float* out = (float*)d_out;

    static cudaStream_t sA = nullptr, sB = nullptr;
    static cudaEvent_t evFork = nullptr, evA = nullptr, evB = nullptr;
    if (!sA) {
        cudaStreamCreateWithFlags(&sA, cudaStreamNonBlocking);
        cudaStreamCreateWithFlags(&sB, cudaStreamNonBlocking);
        cudaEventCreateWithFlags(&evFork, cudaEventDisableTiming);
        cudaEventCreateWithFlags(&evA, cudaEventDisableTiming);
        cudaEventCreateWithFlags(&evB, cudaEventDisableTiming);
        cudaFuncSetAttribute(fattn, cudaFuncAttributeMaxDynamicSharedMemorySize, ATTN_SMEM);
        cudaFuncSetAttribute(fattn_dil, cudaFuncAttributeMaxDynamicSharedMemorySize, ATTN_SMEM);
        cudaFuncSetAttribute(gemm128, cudaFuncAttributeMaxDynamicSharedMemorySize, GEMM_SMEM);
    }

    float* hB   = SYMF(g_h);
    float* qnB  = SYMF(g_qn);
    float* knB  = SYMF(g_kn);
    float* qn2B = SYMF(g_qn2);
    float* kn2B = SYMF(g_kn2);
    float* qn3B = SYMF(g_qn3);
    float* kn3B = SYMF(g_kn3);
    float* QaB  = SYMF(g_Qa);
    float* KVaB = SYMF(g_KVa);
    float* OaB  = SYMF(g_Oa);
    float* partaB = SYMF(g_parta);
    float* QbB  = SYMF(g_Qb);
    float* KVbB = SYMF(g_KVb);
    float* ObB  = SYMF(g_Ob);
    float* partbB = SYMF(g_partb);
    float* oLB  = SYMF(g_oL);
    float* oDB  = SYMF(g_oD);
    float* xlatB= SYMF(g_xlat);
    float* xmemB= SYMF(g_xmem);
    float* x1B  = SYMF(g_x1);
    float* hnB  = SYMF(g_hn);
    float* latprevB = SYMF(g_latprev);
    float* latB  = SYMF(g_lat);
    float* latqB = SYMF(g_latq);
    float* latkB = SYMF(g_latk);
    float* memprevB = SYMF(g_memprev);
    float* memB  = SYMF(g_mem);
    float* memqB = SYMF(g_memq);
    float* memkB = SYMF(g_memk);
    float* uB    = SYMF(g_u);
    float* gactB = SYMF(g_gact);

    const int rowsBL = Bdim * Ldim;

    // prologue: h, then ALL six norms of h in one pass
    rmsnorm_k<<<rowsBL, 256>>>(x, norm_w, hB);
    rmsnorm6_k<<<rowsBL, 256>>>(hB,
                                ld_nq, qnB,  ld_nk, knB,
                                lp_nk, kn2B, lp_nq, qn2B,
                                mem_nk, kn3B, mem_nq, qn3B);
    cudaEventRecord(evFork, 0);
    cudaStreamWaitEvent(sA, evFork, 0);
    cudaStreamWaitEvent(sB, evFork, 0);

    // ---- stream A: local branch, then latent chain ----
    run_mha(qnB, knB, local_w, Ldim, Ldim, 1, kpm, nullptr, oLB, QaB, KVaB, OaB, partaB, sA);

    broadcast_k<<<(BKD+255)/256, 256, 0, sA>>>(lat_tokens, latprevB, KLAT*Ddim - 1, BKD);
    rmsnorm_k<<<Bdim*KLAT, 256, 0, sA>>>(latprevB, lp_nq, latqB);
    run_mha(latqB, kn2B, lat_to_w, KLAT, Ldim, 0, kpm, latprevB, latB, QaB, KVaB, OaB, partaB, sA);
    rmsnorm_k<<<Bdim*KLAT, 256, 0, sA>>>(latB, lp_nk, latkB);
    run_mha(qn2B, latkB, lat_from_w, Ldim, KLAT, 0, nullptr, hB, xlatB, QaB, KVaB, OaB, partaB, sA);
    copy_k<<<(BKD+255)/256, 256, 0, sA>>>(latB, out + (size_t)BLD, BKD);
    cudaEventRecord(evA, sA);

    // ---- stream B: dilated branch, then memory chain ----
    run_mha(qnB, knB, dil_w, Ldim, Ldim, 2, kpm, nullptr, oDB, QbB, KVbB, ObB, partbB, sB);

    broadcast_k<<<(BMD+255)/256, 256, 0, sB>>>(mem_tokens, memprevB, MMEM*Ddim - 1, BMD);
    rmsnorm_k<<<Bdim*MMEM, 256, 0, sB>>>(memprevB, mem_nq, memqB);
    // mem = prev + 0.1*delta : EMA folded into the O-projection reduce (alpha=0.1)
    run_mha(memqB, kn3B, mem_write_w, MMEM, Ldim, 0, kpm, memprevB, memB, QbB, KVbB, ObB, partbB, sB, 0.1f);
    rmsnorm_k<<<Bdim*MMEM, 256, 0, sB>>>(memB, mem_nk, memkB);
    run_mha(qn3B, memkB, mem_read_w, Ldim, MMEM, 0, nullptr, hB, xmemB, QbB, KVbB, ObB, partbB, sB);
    copy_k<<<(BMD+255)/256, 256, 0, sB>>>(memB, out + (size_t)BLD + BKD, BMD);
    cudaEventRecord(evB, sB);

    // ---- join, then fused gate+norm + FFN on the capture stream ----
    cudaStreamWaitEvent(0, evA, 0);
    cudaStreamWaitEvent(0, evB, 0);

    gate_fuse_norm<<<rowsBL, 256>>>(x, hB, oLB, oDB, xlatB, xmemB,
                                    gate_w, gate_b, norm_w, x1B, hnB);

    gemm128<<<dim3(2*DFFdim/128, rowsBL/128, 1), 256, GEMM_SMEM>>>(hnB, up_w, nullptr, uB,
                                                        rowsBL, 2*DFFdim, Ddim, Ddim);
    int n4 = rowsBL * DFFdim / 4;
    silu_mul_k<<<(n4+255)/256, 256>>>(uB, gactB, n4);
    // down-proj split-K=2 (measured best: fills the solo capture stream)
    gemm128<<<dim3(Ddim/128, rowsBL/128, 2), 256, GEMM_SMEM>>>(gactB, down_w, nullptr, partaB,
                                                    rowsBL, Ddim, DFFdim, DFFdim/2);
    reduce_splitk<<<(BLD+255)/256, 256>>>(partaB, x1B, out, BLD, 2, 1.f);
}